// round 14
// baseline (speedup 1.0000x reference)
#include <cuda_runtime.h>
#include <cuda_fp16.h>
#include <math.h>
#include <stdint.h>

// Problem constants
constexpr int Bb    = 2;
constexpr int Ss    = 1024;
constexpr int Dd    = 1024;
constexpr int Hh    = 8;
constexpr int HD    = 128;
constexpr int DEPTH = 8;
constexpr int FF    = 4096;
constexpr int BS    = Bb * Ss;      // 2048

// Scratch (device globals: allocation-free)
__device__ float  g_x  [BS * Dd];
__device__ __half g_xn [BS * Dd];
__device__ __half g_qkv[(size_t)BS * 3 * Dd];            // q | k | v packed (half)
__device__ __half g_wqkvT[(size_t)DEPTH * 3 * Dd * Dd];  // [Wq|Wkv]^T [3D][D] half
__device__ __half g_woT [(size_t)DEPTH * Dd * Dd];       // Wo^T  [D][D] half
__device__ __half g_w1T [(size_t)DEPTH * FF * Dd];       // W1^T  [FF][D] half
__device__ __half g_w2T [(size_t)DEPTH * Dd * FF];       // W2^T  [D][FF] half
__device__ float  g_part2[(size_t)DEPTH * Bb * Hh * 8 * 1024]; // per (l,bh,qb) colsums
__device__ __half g_y  [BS * Dd];
__device__ __half g_ff [(size_t)BS * FF];
__device__ float  g_red[(size_t)4 * BS * Dd];            // split-K partials (fp32)

// ---------------------------------------------------------------- mma / ldmatrix
__device__ __forceinline__ void mma_f16(float* c, const unsigned* a, const unsigned* b) {
    asm volatile(
        "mma.sync.aligned.m16n8k16.row.col.f32.f16.f16.f32 "
        "{%0,%1,%2,%3}, {%4,%5,%6,%7}, {%8,%9}, {%0,%1,%2,%3};"
        : "+f"(c[0]), "+f"(c[1]), "+f"(c[2]), "+f"(c[3])
        : "r"(a[0]), "r"(a[1]), "r"(a[2]), "r"(a[3]), "r"(b[0]), "r"(b[1]));
}
__device__ __forceinline__ void ldsm4(unsigned& r0, unsigned& r1, unsigned& r2,
                                      unsigned& r3, unsigned addr) {
    asm volatile("ldmatrix.sync.aligned.m8n8.x4.shared.b16 {%0,%1,%2,%3}, [%4];"
                 : "=r"(r0), "=r"(r1), "=r"(r2), "=r"(r3) : "r"(addr));
}
__device__ __forceinline__ void ldsm4t(unsigned& r0, unsigned& r1, unsigned& r2,
                                       unsigned& r3, unsigned addr) {
    asm volatile("ldmatrix.sync.aligned.m8n8.x4.trans.shared.b16 {%0,%1,%2,%3}, [%4];"
                 : "=r"(r0), "=r"(r1), "=r"(r2), "=r"(r3) : "r"(addr));
}
__device__ __forceinline__ void cp_async16(unsigned saddr, const void* gptr) {
    asm volatile("cp.async.cg.shared.global [%0], [%1], 16;"
                 :: "r"(saddr), "l"(gptr));
}
#define CP_COMMIT() asm volatile("cp.async.commit_group;")
#define CP_WAIT2()  asm volatile("cp.async.wait_group 2;")
#define CP_WAIT1()  asm volatile("cp.async.wait_group 1;")

__device__ __forceinline__ unsigned h2u(float a, float b) {
    __half2 h = __floats2half2_rn(a, b);
    return *(unsigned*)&h;
}

// ---------------------------------------------------------------- fp16 tensor-core GEMM (weight GEMMs)
#define BM 128
#define BN 128
#define BKH 32
#define AL 40
#define BLN 136
#define STAGES 4
constexpr int AH_ST = BM * AL;
constexpr int BH_ST = 5120;
constexpr int GEMM_SMEM = STAGES * (AH_ST + BH_ST) * 2;   // 81920 B

template<int EPI, bool TRANSB, bool OUTHALF>
__global__ __launch_bounds__(128, 2) void gemm_h(
    const __half* __restrict__ A, const __half* __restrict__ Bg,
    void* __restrict__ Cv,
    int K, int lda, int ldb, int ldc,
    long long sAo, long long sAi, long long sBo, long long sBi,
    long long sCo, long long sCi, int zdiv,
    float alpha, int causal)
{
    const int bm = blockIdx.y * BM;
    const int bn = blockIdx.x * BN;
    if (causal == 1 && bn >= bm + BM) return;
    const int Keff = (causal == 2) ? min(K, bm + BM) : K;

    const int z  = blockIdx.z;
    const int zo = z / zdiv;
    const int zi = z - zo * zdiv;
    A  += zo * sAo + zi * sAi;
    Bg += zo * sBo + zi * sBi;
    const long long coff = zo * sCo + zi * sCi;
    __half* Ch = (__half*)Cv + coff;
    float*  Cf = (float*)Cv + coff;

    extern __shared__ __align__(16) char smem_raw[];
    const unsigned asb = (unsigned)__cvta_generic_to_shared(smem_raw);
    const unsigned bsb = asb + (unsigned)(STAGES * AH_ST * 2);

    const int tid  = threadIdx.x;
    const int lane = tid & 31;
    const int warp = tid >> 5;
    const int wm   = (warp & 1) * 64;
    const int wn   = (warp >> 1) * 64;
    const int g    = lane >> 2;
    const int t    = lane & 3;

    const int lp = lane >> 3;
    const int lr = lane & 7;
    const int aRowOff  = (lp & 1) * 8 + lr;
    const int aColOff  = (lp >> 1) * 8;
    const int bRowOff  = (lp >> 1) * 8 + lr;
    const int bColOff  = (lp & 1) * 8;
    const int ntRowOff = (lp & 1) * 8 + lr;
    const int ntColOff = (lp >> 1) * 8;

    float acc[4][8][4];
    #pragma unroll
    for (int i = 0; i < 4; i++)
        #pragma unroll
        for (int j = 0; j < 8; j++)
            #pragma unroll
            for (int r = 0; r < 4; r++) acc[i][j][r] = 0.f;

    auto issue = [&](int s, int k0) {
        const unsigned aB = asb + (unsigned)(s * AH_ST * 2);
        #pragma unroll
        for (int h = 0; h < 4; h++) {
            int row = (tid >> 2) + 32 * h;
            cp_async16(aB + (unsigned)((row * AL + (tid & 3) * 8) * 2),
                       &A[(long long)(bm + row) * lda + k0 + (tid & 3) * 8]);
        }
        const unsigned bB = bsb + (unsigned)(s * BH_ST * 2);
        if (TRANSB) {
            #pragma unroll
            for (int h = 0; h < 4; h++) {
                int row = (tid >> 2) + 32 * h;
                cp_async16(bB + (unsigned)((row * AL + (tid & 3) * 8) * 2),
                           &Bg[(long long)(bn + row) * ldb + k0 + (tid & 3) * 8]);
            }
        } else {
            #pragma unroll
            for (int h = 0; h < 4; h++) {
                int idx = h * 128 + tid;
                int kr  = idx >> 4;
                int ch  = idx & 15;
                cp_async16(bB + (unsigned)((kr * BLN + ch * 8) * 2),
                           &Bg[(long long)(k0 + kr) * ldb + bn + ch * 8]);
            }
        }
    };

    auto compute = [&](int p) {
        const unsigned abase = asb + (unsigned)(p * AH_ST * 2)
                             + (unsigned)(((wm + aRowOff) * AL + aColOff) * 2);
        unsigned bbase;
        if (TRANSB)
            bbase = bsb + (unsigned)(p * BH_ST * 2)
                  + (unsigned)(((wn + bRowOff) * AL + bColOff) * 2);
        else
            bbase = bsb + (unsigned)(p * BH_ST * 2)
                  + (unsigned)((ntRowOff * BLN + wn + ntColOff) * 2);
        #pragma unroll
        for (int ks = 0; ks < 2; ks++) {
            const int kk = ks * 16;
            unsigned af[4][4], bf[8][2];
            #pragma unroll
            for (int i = 0; i < 4; i++)
                ldsm4(af[i][0], af[i][1], af[i][2], af[i][3],
                      abase + (unsigned)((i * 16 * AL + kk) * 2));
            if (TRANSB) {
                #pragma unroll
                for (int jp = 0; jp < 4; jp++) {
                    unsigned r0, r1, r2, r3;
                    ldsm4(r0, r1, r2, r3, bbase + (unsigned)((jp * 16 * AL + kk) * 2));
                    bf[2 * jp][0] = r0; bf[2 * jp][1] = r1;
                    bf[2 * jp + 1][0] = r2; bf[2 * jp + 1][1] = r3;
                }
            } else {
                #pragma unroll
                for (int jp = 0; jp < 4; jp++) {
                    unsigned r0, r1, r2, r3;
                    ldsm4t(r0, r1, r2, r3,
                           bbase + (unsigned)((kk * BLN + jp * 16) * 2));
                    bf[2 * jp][0] = r0; bf[2 * jp][1] = r1;
                    bf[2 * jp + 1][0] = r2; bf[2 * jp + 1][1] = r3;
                }
            }
            #pragma unroll
            for (int i = 0; i < 4; i++)
                #pragma unroll
                for (int j = 0; j < 8; j++)
                    mma_f16(acc[i][j], af[i], bf[j]);
        }
    };

    const int nk = Keff / BKH;
    #pragma unroll
    for (int s = 0; s < STAGES - 1; s++) {
        if (s < nk) issue(s, s * BKH);
        CP_COMMIT();
    }
    for (int kt = 0; kt < nk; kt++) {
        CP_WAIT2();
        __syncthreads();
        compute(kt % STAGES);
        if (kt + STAGES - 1 < nk)
            issue((kt + STAGES - 1) % STAGES, (kt + STAGES - 1) * BKH);
        CP_COMMIT();
    }

    #pragma unroll
    for (int i = 0; i < 4; i++) {
        #pragma unroll
        for (int j = 0; j < 8; j++) {
            const long long row = bm + wm + i * 16 + g;
            const int       col = bn + wn + j * 8 + 2 * t;
            float2 v0 = make_float2(acc[i][j][0] * alpha, acc[i][j][1] * alpha);
            float2 v1 = make_float2(acc[i][j][2] * alpha, acc[i][j][3] * alpha);
            if (EPI == 2) {
                const float c = 0.70710678118654752f;
                v0.x = 0.5f * v0.x * erfcf(-v0.x * c);
                v0.y = 0.5f * v0.y * erfcf(-v0.y * c);
                v1.x = 0.5f * v1.x * erfcf(-v1.x * c);
                v1.y = 0.5f * v1.y * erfcf(-v1.y * c);
            }
            if (OUTHALF) {
                *(__half2*)&Ch[row * (long long)ldc + col]       = __floats2half2_rn(v0.x, v0.y);
                *(__half2*)&Ch[(row + 8) * (long long)ldc + col] = __floats2half2_rn(v1.x, v1.y);
            } else {
                *(float2*)&Cf[row * (long long)ldc + col]       = v0;
                *(float2*)&Cf[(row + 8) * (long long)ldc + col] = v1;
            }
        }
    }
}

// ---------------------------------------------------------------- flash v2: 2-pass, no P materialization
constexpr int FL_STRIDE = 136;                       // halves
constexpr int FL_TILE   = 128 * FL_STRIDE * 2;       // 34816 B
constexpr int FL_CS     = 8 * 128 * 4;               // 4096 B warp colsum buffer
constexpr int FL_SMEM   = 4 * FL_TILE + FL_CS;       // 143360 B

__global__ __launch_bounds__(256, 1) void flash2_k(
    const __half* __restrict__ qkv, float* __restrict__ part2,
    __half* __restrict__ y, float scale2)
{
    const int qb = blockIdx.x;
    const int bh = blockIdx.y;
    const int b  = bh >> 3;
    const int h  = bh & 7;
    const int D3 = 3 * Dd;

    const __half* Qp = qkv + ((long long)(b * Ss + qb * 128)) * D3 + h * HD;
    const __half* Kp = qkv + ((long long)b * Ss) * D3 + Dd + h * HD;
    const __half* Vp = qkv + ((long long)b * Ss) * D3 + 2 * Dd + h * HD;
    __half* yp = y + ((long long)(b * Ss + qb * 128)) * Dd + h * HD;
    float* p2p = part2 + ((size_t)bh * 8 + qb) * 1024;

    extern __shared__ __align__(16) char smemraw[];
    const unsigned sb = (unsigned)__cvta_generic_to_shared(smemraw);
    const unsigned kB0 = sb, kB1 = sb + FL_TILE;
    const unsigned vB0 = sb + 2 * FL_TILE, vB1 = sb + 3 * FL_TILE;
    float* sm_cs = (float*)(smemraw + 4 * FL_TILE);

    const int tid  = threadIdx.x;
    const int lane = tid & 31;
    const int warp = tid >> 5;
    const int wq   = warp * 16;
    const int g    = lane >> 2;
    const int t    = lane & 3;
    const int lp = lane >> 3, lr = lane & 7;
    const int aRowOff  = (lp & 1) * 8 + lr;
    const int aColOff  = (lp >> 1) * 8;
    const int bRowOff  = (lp >> 1) * 8 + lr;
    const int bColOff  = (lp & 1) * 8;
    const int ntRowOff = (lp & 1) * 8 + lr;
    const int ntColOff = (lp >> 1) * 8;

    auto loadTile = [&](unsigned dstB, const __half* src) {
        #pragma unroll
        for (int i2 = 0; i2 < 8; i2++) {
            int idx = i2 * 256 + tid;
            int r = idx >> 4, ch = idx & 15;
            cp_async16(dstB + (unsigned)((r * FL_STRIDE + ch * 8) * 2),
                       src + (long long)r * D3 + ch * 8);
        }
    };

    loadTile(vB0, Qp); CP_COMMIT();
    loadTile(kB0, Kp); CP_COMMIT();
    CP_WAIT1();
    __syncthreads();
    unsigned aQ[8][4];
    {
        const unsigned abase = vB0 + (unsigned)(((wq + aRowOff) * FL_STRIDE + aColOff) * 2);
        #pragma unroll
        for (int ks = 0; ks < 8; ks++)
            ldsm4(aQ[ks][0], aQ[ks][1], aQ[ks][2], aQ[ks][3],
                  abase + (unsigned)(ks * 32));
    }

    const int rloc0 = wq + g, rloc1 = rloc0 + 8;
    float m0 = -1e30f, m1 = -1e30f, l0 = 0.f, l1 = 0.f;

    auto computeS = [&](unsigned kbuf, float (*ct)[4], bool diag) {
        #pragma unroll
        for (int nt = 0; nt < 16; nt++) {
            ct[nt][0] = 0.f; ct[nt][1] = 0.f; ct[nt][2] = 0.f; ct[nt][3] = 0.f;
        }
        const unsigned bbase = kbuf + (unsigned)((bRowOff * FL_STRIDE + bColOff) * 2);
        #pragma unroll
        for (int ks = 0; ks < 8; ks++) {
            unsigned bf[16][2];
            #pragma unroll
            for (int jp = 0; jp < 8; jp++) {
                unsigned r0, r1, r2, r3;
                ldsm4(r0, r1, r2, r3,
                      bbase + (unsigned)((jp * 16 * FL_STRIDE + ks * 16) * 2));
                bf[2 * jp][0] = r0; bf[2 * jp][1] = r1;
                bf[2 * jp + 1][0] = r2; bf[2 * jp + 1][1] = r3;
            }
            #pragma unroll
            for (int nt = 0; nt < 16; nt++)
                mma_f16(ct[nt], aQ[ks], bf[nt]);
        }
        #pragma unroll
        for (int nt = 0; nt < 16; nt++) {
            #pragma unroll
            for (int e = 0; e < 2; e++) {
                float s0 = ct[nt][e]     * scale2;
                float s1 = ct[nt][2 + e] * scale2;
                if (diag) {
                    int col = nt * 8 + 2 * t + e;
                    if (col > rloc0) s0 = -1e30f;
                    if (col > rloc1) s1 = -1e30f;
                }
                ct[nt][e] = s0; ct[nt][2 + e] = s1;
            }
        }
    };

    // pass 1: softmax stats
    for (int kb = 0; kb <= qb; kb++) {
        const int cur = kb & 1;
        if (kb < qb) loadTile(cur ? kB0 : kB1, Kp + (long long)(kb + 1) * 128 * D3);
        CP_COMMIT();
        CP_WAIT1();
        __syncthreads();

        float ct[16][4];
        computeS(cur ? kB1 : kB0, ct, kb == qb);

        float mx0 = -1e30f, mx1 = -1e30f;
        #pragma unroll
        for (int nt = 0; nt < 16; nt++) {
            mx0 = fmaxf(mx0, fmaxf(ct[nt][0], ct[nt][1]));
            mx1 = fmaxf(mx1, fmaxf(ct[nt][2], ct[nt][3]));
        }
        mx0 = fmaxf(mx0, __shfl_xor_sync(0xffffffffu, mx0, 1));
        mx0 = fmaxf(mx0, __shfl_xor_sync(0xffffffffu, mx0, 2));
        mx1 = fmaxf(mx1, __shfl_xor_sync(0xffffffffu, mx1, 1));
        mx1 = fmaxf(mx1, __shfl_xor_sync(0xffffffffu, mx1, 2));
        const float m0n = fmaxf(m0, mx0), m1n = fmaxf(m1, mx1);
        const float f0 = exp2f(m0 - m0n), f1 = exp2f(m1 - m1n);
        float rs0 = 0.f, rs1 = 0.f;
        #pragma unroll
        for (int nt = 0; nt < 16; nt++) {
            rs0 += exp2f(ct[nt][0] - m0n) + exp2f(ct[nt][1] - m0n);
            rs1 += exp2f(ct[nt][2] - m1n) + exp2f(ct[nt][3] - m1n);
        }
        rs0 += __shfl_xor_sync(0xffffffffu, rs0, 1);
        rs0 += __shfl_xor_sync(0xffffffffu, rs0, 2);
        rs1 += __shfl_xor_sync(0xffffffffu, rs1, 1);
        rs1 += __shfl_xor_sync(0xffffffffu, rs1, 2);
        l0 = l0 * f0 + rs0;
        l1 = l1 * f1 + rs1;
        m0 = m0n; m1 = m1n;
        __syncthreads();
    }
    const float inv0 = 1.f / l0, inv1 = 1.f / l1;

    // pass 2: P, O, column sums
    float oc[16][4];
    #pragma unroll
    for (int nt = 0; nt < 16; nt++) {
        oc[nt][0] = 0.f; oc[nt][1] = 0.f; oc[nt][2] = 0.f; oc[nt][3] = 0.f;
    }
    loadTile(kB0, Kp); loadTile(vB0, Vp); CP_COMMIT();
    for (int kb = 0; kb <= qb; kb++) {
        const int cur = kb & 1;
        if (kb < qb) {
            loadTile(cur ? kB0 : kB1, Kp + (long long)(kb + 1) * 128 * D3);
            loadTile(cur ? vB0 : vB1, Vp + (long long)(kb + 1) * 128 * D3);
        }
        CP_COMMIT();
        CP_WAIT1();
        __syncthreads();

        float ct[16][4];
        computeS(cur ? kB1 : kB0, ct, kb == qb);
        #pragma unroll
        for (int nt = 0; nt < 16; nt++) {
            ct[nt][0] = exp2f(ct[nt][0] - m0) * inv0;
            ct[nt][1] = exp2f(ct[nt][1] - m0) * inv0;
            ct[nt][2] = exp2f(ct[nt][2] - m1) * inv1;
            ct[nt][3] = exp2f(ct[nt][3] - m1) * inv1;
        }

        #pragma unroll
        for (int nt = 0; nt < 16; nt++) {
            float c0 = ct[nt][0] + ct[nt][2];
            float c1 = ct[nt][1] + ct[nt][3];
            c0 += __shfl_xor_sync(0xffffffffu, c0, 4);
            c0 += __shfl_xor_sync(0xffffffffu, c0, 8);
            c0 += __shfl_xor_sync(0xffffffffu, c0, 16);
            c1 += __shfl_xor_sync(0xffffffffu, c1, 4);
            c1 += __shfl_xor_sync(0xffffffffu, c1, 8);
            c1 += __shfl_xor_sync(0xffffffffu, c1, 16);
            if (lane < 4) {
                sm_cs[warp * 128 + nt * 8 + 2 * t]     = c0;
                sm_cs[warp * 128 + nt * 8 + 2 * t + 1] = c1;
            }
        }

        {
            const unsigned vbase = (cur ? vB1 : vB0)
                                 + (unsigned)((ntRowOff * FL_STRIDE + ntColOff) * 2);
            #pragma unroll
            for (int ks = 0; ks < 8; ks++) {
                unsigned aP[4];
                aP[0] = h2u(ct[2 * ks][0],     ct[2 * ks][1]);
                aP[1] = h2u(ct[2 * ks][2],     ct[2 * ks][3]);
                aP[2] = h2u(ct[2 * ks + 1][0], ct[2 * ks + 1][1]);
                aP[3] = h2u(ct[2 * ks + 1][2], ct[2 * ks + 1][3]);
                unsigned bf[16][2];
                #pragma unroll
                for (int jp = 0; jp < 8; jp++) {
                    unsigned r0, r1, r2, r3;
                    ldsm4t(r0, r1, r2, r3,
                           vbase + (unsigned)((ks * 16 * FL_STRIDE + jp * 16) * 2));
                    bf[2 * jp][0] = r0; bf[2 * jp][1] = r1;
                    bf[2 * jp + 1][0] = r2; bf[2 * jp + 1][1] = r3;
                }
                #pragma unroll
                for (int nt = 0; nt < 16; nt++)
                    mma_f16(oc[nt], aP, bf[nt]);
            }
        }
        __syncthreads();
        if (tid < 128) {
            float s = 0.f;
            #pragma unroll
            for (int w = 0; w < 8; w++) s += sm_cs[w * 128 + tid];
            p2p[kb * 128 + tid] = s;
        }
        __syncthreads();
    }

    __half2* y0 = (__half2*)(yp + (long long)rloc0 * Dd + 2 * t);
    __half2* y1 = (__half2*)(yp + (long long)rloc1 * Dd + 2 * t);
    #pragma unroll
    for (int nt = 0; nt < 16; nt++) {
        y0[nt * 4] = __floats2half2_rn(oc[nt][0], oc[nt][1]);
        y1[nt * 4] = __floats2half2_rn(oc[nt][2], oc[nt][3]);
    }
}

// ---------------------------------------------------------------- final amap (fixed order over l, h, qb)
__global__ __launch_bounds__(256) void amap_fin_k(
    const float* __restrict__ part2, float* __restrict__ amap)
{
    const int i = blockIdx.x * 256 + threadIdx.x;   // 0..2047
    const int b = i >> 10, k = i & 1023;
    const int qb0 = k >> 7;
    float s = 0.f;
    for (int l = 0; l < DEPTH; l++)
        for (int h = 0; h < Hh; h++)
            for (int qb = qb0; qb < 8; qb++)
                s += part2[((((size_t)l * Bb * Hh) + (size_t)(b * Hh + h)) * 8 + qb) * 1024 + k];
    amap[i] = s;
}

// ---------------------------------------------------------------- fused split-K reduce (+bias)(+snapshot)(+LN -> half xn)
template<int P, bool BIAS, bool SNAP, bool OUTLN>
__global__ __launch_bounds__(256) void reduce_ln_k(
    const float4* __restrict__ part, float4* __restrict__ x,
    const float* __restrict__ bias, float4* __restrict__ st, int layer,
    const float* __restrict__ g, const float* __restrict__ b,
    __half* __restrict__ xn)
{
    __shared__ float sm0[8], sm1[8];
    const int row = blockIdx.x, tid = threadIdx.x;
    const int i = row * 256 + tid;
    constexpr int N4 = BS * Dd / 4;

    float4 s = part[i];
    #pragma unroll
    for (int p = 1; p < P; p++) {
        float4 v = part[(size_t)p * N4 + i];
        s.x += v.x; s.y += v.y; s.z += v.z; s.w += v.w;
    }
    if (BIAS) {
        float4 bb = ((const float4*)bias)[tid];
        s.x += bb.x; s.y += bb.y; s.z += bb.z; s.w += bb.w;
    }
    float4 v = x[i];
    v.x += s.x; v.y += s.y; v.z += s.z; v.w += s.w;
    x[i] = v;
    if (SNAP)
        st[((long long)row * DEPTH + layer) * 256 + tid] = v;

    if (OUTLN) {
        float su  = v.x + v.y + v.z + v.w;
        float su2 = v.x * v.x + v.y * v.y + v.z * v.z + v.w * v.w;
        #pragma unroll
        for (int o = 16; o > 0; o >>= 1) {
            su  += __shfl_xor_sync(0xffffffffu, su,  o);
            su2 += __shfl_xor_sync(0xffffffffu, su2, o);
        }
        if ((tid & 31) == 0) { sm0[tid >> 5] = su; sm1[tid >> 5] = su2; }
        __syncthreads();
        if (tid < 32) {
            su  = (tid < 8) ? sm0[tid] : 0.f;
            su2 = (tid < 8) ? sm1[tid] : 0.f;
            #pragma unroll
            for (int o = 4; o > 0; o >>= 1) {
                su  += __shfl_xor_sync(0xffffffffu, su,  o);
                su2 += __shfl_xor_sync(0xffffffffu, su2, o);
            }
            if (tid == 0) { sm0[0] = su; sm1[0] = su2; }
        }
        __syncthreads();
        const float mean = sm0[0] * (1.f / Dd);
        const float var  = sm1[0] * (1.f / Dd) - mean * mean;
        const float rstd = rsqrtf(var + 1e-5f);
        float4 gg = ((const float4*)g)[tid];
        float4 bb = ((const float4*)b)[tid];
        float4 o;
        o.x = (v.x - mean) * rstd * gg.x + bb.x;
        o.y = (v.y - mean) * rstd * gg.y + bb.y;
        o.z = (v.z - mean) * rstd * gg.z + bb.z;
        o.w = (v.w - mean) * rstd * gg.w + bb.w;
        __half2* oh = (__half2*)(xn + (long long)row * Dd);
        oh[2 * tid]     = __floats2half2_rn(o.x, o.y);
        oh[2 * tid + 1] = __floats2half2_rn(o.z, o.w);
    }
}

// ---------------------------------------------------------------- transpose + cvt to half (half2-packed writes)
// dst[c][r] = half(src[r][c]); tile 64 src-rows x 32 src-cols
__global__ __launch_bounds__(256) void transpose_cvt_k(
    const float* __restrict__ src, __half* __restrict__ dst,
    int R, int C, long long sSrc, long long sDst)
{
    __shared__ float tile[64][33];
    src += blockIdx.z * sSrc;
    dst += blockIdx.z * sDst;
    const int c0 = blockIdx.x * 32, r0 = blockIdx.y * 64;
    const int tid = threadIdx.x;
    #pragma unroll
    for (int it = 0; it < 8; it++) {
        int idx = it * 256 + tid;
        int r = idx >> 5, c = idx & 31;
        tile[r][c] = src[(long long)(r0 + r) * C + c0 + c];
    }
    __syncthreads();
    #pragma unroll
    for (int it = 0; it < 4; it++) {
        int idx = it * 256 + tid;
        int c = idx >> 5, j = idx & 31;
        __half2 h = __floats2half2_rn(tile[2 * j][c], tile[2 * j + 1][c]);
        *((__half2*)(dst + (long long)(c0 + c) * R + r0) + j) = h;
    }
}

// ---------------------------------------------------------------- LayerNorm (standalone)
template<bool OUTH>
__global__ __launch_bounds__(256) void ln_k(
    const float* __restrict__ x, const float* __restrict__ g,
    const float* __restrict__ b, void* __restrict__ outv)
{
    __shared__ float sm0[8], sm1[8];
    const int row = blockIdx.x, tid = threadIdx.x;
    float4 v = ((const float4*)(x + (long long)row * Dd))[tid];
    float s  = v.x + v.y + v.z + v.w;
    float s2 = v.x * v.x + v.y * v.y + v.z * v.z + v.w * v.w;
    #pragma unroll
    for (int o = 16; o > 0; o >>= 1) {
        s  += __shfl_xor_sync(0xffffffffu, s,  o);
        s2 += __shfl_xor_sync(0xffffffffu, s2, o);
    }
    if ((tid & 31) == 0) { sm0[tid >> 5] = s; sm1[tid >> 5] = s2; }
    __syncthreads();
    if (tid < 32) {
        s  = (tid < 8) ? sm0[tid] : 0.f;
        s2 = (tid < 8) ? sm1[tid] : 0.f;
        #pragma unroll
        for (int o = 4; o > 0; o >>= 1) {
            s  += __shfl_xor_sync(0xffffffffu, s,  o);
            s2 += __shfl_xor_sync(0xffffffffu, s2, o);
        }
        if (tid == 0) { sm0[0] = s; sm1[0] = s2; }
    }
    __syncthreads();
    const float mean = sm0[0] * (1.f / Dd);
    const float var  = sm1[0] * (1.f / Dd) - mean * mean;
    const float rstd = rsqrtf(var + 1e-5f);
    float4 gg = ((const float4*)g)[tid];
    float4 bb = ((const float4*)b)[tid];
    float4 o;
    o.x = (v.x - mean) * rstd * gg.x + bb.x;
    o.y = (v.y - mean) * rstd * gg.y + bb.y;
    o.z = (v.z - mean) * rstd * gg.z + bb.z;
    o.w = (v.w - mean) * rstd * gg.w + bb.w;
    if (OUTH) {
        __half2* oh = (__half2*)((__half*)outv + (long long)row * Dd);
        oh[2 * tid]     = __floats2half2_rn(o.x, o.y);
        oh[2 * tid + 1] = __floats2half2_rn(o.z, o.w);
    } else {
        ((float4*)((float*)outv + (long long)row * Dd))[tid] = o;
    }
}

// ---------------------------------------------------------------- misc
__global__ __launch_bounds__(256) void init_x_snap_k(
    const float4* __restrict__ token, float4* __restrict__ x,
    float4* __restrict__ st)
{
    const int i = blockIdx.x * 256 + threadIdx.x;
    float4 v = token[i];
    x[i] = v;
    st[((long long)(i >> 8) * DEPTH + 0) * 256 + (i & 255)] = v;
}

// ---------------------------------------------------------------- launcher
extern "C" void kernel_launch(void* const* d_in, const int* in_sizes, int n_in,
                              void* d_out, int out_size)
{
    const float* token = (const float*)d_in[0];
    const float* Wq    = (const float*)d_in[1];
    const float* Wkv   = (const float*)d_in[2];
    const float* Wo    = (const float*)d_in[3];
    const float* b_o   = (const float*)d_in[4];
    const float* g1    = (const float*)d_in[5];
    const float* b1    = (const float*)d_in[6];
    const float* g3    = (const float*)d_in[7];
    const float* b3    = (const float*)d_in[8];
    const float* W1    = (const float*)d_in[9];
    const float* W2    = (const float*)d_in[10];
    const float* gout  = (const float*)d_in[11];
    const float* bout  = (const float*)d_in[12];
    float* out = (float*)d_out;

    float *x, *red, *part2;
    __half *xn, *qkv, *wqkvT, *woT, *w1T, *w2T, *y, *ff;
    cudaGetSymbolAddress((void**)&x,     g_x);
    cudaGetSymbolAddress((void**)&xn,    g_xn);
    cudaGetSymbolAddress((void**)&qkv,   g_qkv);
    cudaGetSymbolAddress((void**)&wqkvT, g_wqkvT);
    cudaGetSymbolAddress((void**)&woT,   g_woT);
    cudaGetSymbolAddress((void**)&w1T,   g_w1T);
    cudaGetSymbolAddress((void**)&w2T,   g_w2T);
    cudaGetSymbolAddress((void**)&part2, g_part2);
    cudaGetSymbolAddress((void**)&y,     g_y);
    cudaGetSymbolAddress((void**)&ff,    g_ff);
    cudaGetSymbolAddress((void**)&red,   g_red);

    cudaFuncSetAttribute(gemm_h<0, true,  true >, cudaFuncAttributeMaxDynamicSharedMemorySize, GEMM_SMEM);
    cudaFuncSetAttribute(gemm_h<0, true,  false>, cudaFuncAttributeMaxDynamicSharedMemorySize, GEMM_SMEM);
    cudaFuncSetAttribute(gemm_h<2, true,  true >, cudaFuncAttributeMaxDynamicSharedMemorySize, GEMM_SMEM);
    cudaFuncSetAttribute(flash2_k, cudaFuncAttributeMaxDynamicSharedMemorySize, FL_SMEM);

    float* out_state = out + (size_t)BS * Dd;
    float* amap      = out_state + (size_t)BS * DEPTH * Dd;

    init_x_snap_k<<<BS * Dd / 4 / 256, 256>>>((const float4*)token, (float4*)x,
                                              (float4*)out_state);

    const int D3 = 3 * Dd;
    transpose_cvt_k<<<dim3(Dd / 32, Dd / 64, DEPTH), 256>>>(
        Wq, wqkvT, Dd, Dd, (long long)Dd * Dd, (long long)D3 * Dd);
    transpose_cvt_k<<<dim3(2 * Dd / 32, Dd / 64, DEPTH), 256>>>(
        Wkv, wqkvT + (size_t)Dd * Dd, Dd, 2 * Dd,
        (long long)Dd * 2 * Dd, (long long)D3 * Dd);
    transpose_cvt_k<<<dim3(Dd / 32, Dd / 64, DEPTH), 256>>>(
        Wo, woT, Dd, Dd, (long long)Dd * Dd, (long long)Dd * Dd);
    transpose_cvt_k<<<dim3(FF / 32, Dd / 64, DEPTH), 256>>>(
        W1, w1T, Dd, FF, (long long)Dd * FF, (long long)Dd * FF);
    transpose_cvt_k<<<dim3(Dd / 32, FF / 64, DEPTH), 256>>>(
        W2, w2T, FF, Dd, (long long)FF * Dd, (long long)FF * Dd);

    const float scale2 = rsqrtf((float)HD) * 1.4426950408889634f;   // scale * log2(e)

    // layer-0 LN1
    ln_k<true><<<BS, 256>>>(x, g1, b1, xn);

    for (int l = 0; l < DEPTH; l++) {
        // QKV = xn @ [Wq|Wkv]^T
        gemm_h<0, true, true><<<dim3(D3 / BN, BS / BM, 1), 128, GEMM_SMEM>>>(
            xn, wqkvT + (size_t)l * D3 * Dd, qkv,
            Dd, Dd, Dd, D3, 0, 0, 0, 0, 0, 0, 1, 1.f, 0);
        // fused attention (writes layer-indexed colsum partials)
        flash2_k<<<dim3(8, Bb * Hh), 256, FL_SMEM>>>(
            qkv, part2 + (size_t)l * Bb * Hh * 8 * 1024, y, scale2);
        // Wo GEMM (split-K=2, fp32 partials)
        gemm_h<0, true, false><<<dim3(Dd / BN, BS / BM, 2), 128, GEMM_SMEM>>>(
            y, woT + (size_t)l * Dd * Dd, red,
            Dd / 2, Dd, Dd, Dd,
            0, Dd / 2, 0, Dd / 2,
            0, (long long)BS * Dd,
            2, 1.f, 0);
        reduce_ln_k<2, true, false, true><<<BS, 256>>>(
            (const float4*)red, (float4*)x, b_o + l * Dd, nullptr, 0,
            g3 + l * Dd, b3 + l * Dd, xn);
        // ff = gelu(xn @ W1^T)
        gemm_h<2, true, true><<<dim3(FF / BN, BS / BM, 1), 128, GEMM_SMEM>>>(
            xn, w1T + (size_t)l * FF * Dd, ff,
            Dd, Dd, Dd, FF, 0, 0, 0, 0, 0, 0, 1, 1.f, 0);
        // FF2 GEMM (split-K=4)
        gemm_h<0, true, false><<<dim3(Dd / BN, BS / BM, 4), 128, GEMM_SMEM>>>(
            ff, w2T + (size_t)l * Dd * FF, red,
            FF / 4, FF, FF, Dd,
            0, FF / 4, 0, FF / 4,
            0, (long long)BS * Dd,
            4, 1.f, 0);
        if (l < DEPTH - 1)
            reduce_ln_k<4, false, true, true><<<BS, 256>>>(
                (const float4*)red, (float4*)x, nullptr, (float4*)out_state, l + 1,
                g1 + (l + 1) * Dd, b1 + (l + 1) * Dd, xn);
        else
            reduce_ln_k<4, false, false, false><<<BS, 256>>>(
                (const float4*)red, (float4*)x, nullptr, nullptr, 0,
                nullptr, nullptr, nullptr);
    }
    // single deterministic amap accumulation over all layers
    amap_fin_k<<<Bb * Ss / 256, 256>>>(part2, amap);
    // final LN -> x_out (fp32)
    ln_k<false><<<BS, 256>>>(x, gout, bout, out);
}

// round 15
// speedup vs baseline: 1.0242x; 1.0242x over previous
#include <cuda_runtime.h>
#include <cuda_fp16.h>
#include <math.h>
#include <stdint.h>

// Problem constants
constexpr int Bb    = 2;
constexpr int Ss    = 1024;
constexpr int Dd    = 1024;
constexpr int Hh    = 8;
constexpr int HD    = 128;
constexpr int DEPTH = 8;
constexpr int FF    = 4096;
constexpr int BS    = Bb * Ss;      // 2048

// Scratch (device globals: allocation-free)
__device__ float  g_x  [BS * Dd];
__device__ __half g_xn [BS * Dd];
__device__ __half g_qkv[(size_t)BS * 3 * Dd];            // q | k | v packed (half)
__device__ __half g_wqkvT[(size_t)DEPTH * 3 * Dd * Dd];  // [Wq|Wkv]^T [3D][D] half
__device__ __half g_woT [(size_t)DEPTH * Dd * Dd];       // Wo^T  [D][D] half
__device__ __half g_w1T [(size_t)DEPTH * FF * Dd];       // W1^T  [FF][D] half
__device__ __half g_w2T [(size_t)DEPTH * Dd * FF];       // W2^T  [D][FF] half
__device__ float  g_part2[(size_t)Bb * Hh * 8 * 1024];   // per (bh, qb) column sums
__device__ __half g_y  [BS * Dd];
__device__ __half g_ff [(size_t)BS * FF];
__device__ float  g_red[(size_t)4 * BS * Dd];            // split-K partials (fp32)

// ---------------------------------------------------------------- mma / ldmatrix
__device__ __forceinline__ void mma_f16(float* c, const unsigned* a, const unsigned* b) {
    asm volatile(
        "mma.sync.aligned.m16n8k16.row.col.f32.f16.f16.f32 "
        "{%0,%1,%2,%3}, {%4,%5,%6,%7}, {%8,%9}, {%0,%1,%2,%3};"
        : "+f"(c[0]), "+f"(c[1]), "+f"(c[2]), "+f"(c[3])
        : "r"(a[0]), "r"(a[1]), "r"(a[2]), "r"(a[3]), "r"(b[0]), "r"(b[1]));
}
__device__ __forceinline__ void ldsm4(unsigned& r0, unsigned& r1, unsigned& r2,
                                      unsigned& r3, unsigned addr) {
    asm volatile("ldmatrix.sync.aligned.m8n8.x4.shared.b16 {%0,%1,%2,%3}, [%4];"
                 : "=r"(r0), "=r"(r1), "=r"(r2), "=r"(r3) : "r"(addr));
}
__device__ __forceinline__ void ldsm4t(unsigned& r0, unsigned& r1, unsigned& r2,
                                       unsigned& r3, unsigned addr) {
    asm volatile("ldmatrix.sync.aligned.m8n8.x4.trans.shared.b16 {%0,%1,%2,%3}, [%4];"
                 : "=r"(r0), "=r"(r1), "=r"(r2), "=r"(r3) : "r"(addr));
}
__device__ __forceinline__ void cp_async16(unsigned saddr, const void* gptr) {
    asm volatile("cp.async.cg.shared.global [%0], [%1], 16;"
                 :: "r"(saddr), "l"(gptr));
}
#define CP_COMMIT() asm volatile("cp.async.commit_group;")
#define CP_WAIT2()  asm volatile("cp.async.wait_group 2;")
#define CP_WAIT1()  asm volatile("cp.async.wait_group 1;")

__device__ __forceinline__ unsigned h2u(float a, float b) {
    __half2 h = __floats2half2_rn(a, b);
    return *(unsigned*)&h;
}

// ---------------------------------------------------------------- fp16 tensor-core GEMM (weight GEMMs)
#define BM 128
#define BN 128
#define BKH 32
#define AL 40
#define BLN 136
#define STAGES 4
constexpr int AH_ST = BM * AL;
constexpr int BH_ST = 5120;
constexpr int GEMM_SMEM = STAGES * (AH_ST + BH_ST) * 2;   // 81920 B

template<int EPI, bool TRANSB, bool OUTHALF>
__global__ __launch_bounds__(128, 2) void gemm_h(
    const __half* __restrict__ A, const __half* __restrict__ Bg,
    void* __restrict__ Cv,
    int K, int lda, int ldb, int ldc,
    long long sAo, long long sAi, long long sBo, long long sBi,
    long long sCo, long long sCi, int zdiv,
    float alpha, int causal)
{
    const int bm = blockIdx.y * BM;
    const int bn = blockIdx.x * BN;
    if (causal == 1 && bn >= bm + BM) return;
    const int Keff = (causal == 2) ? min(K, bm + BM) : K;

    const int z  = blockIdx.z;
    const int zo = z / zdiv;
    const int zi = z - zo * zdiv;
    A  += zo * sAo + zi * sAi;
    Bg += zo * sBo + zi * sBi;
    const long long coff = zo * sCo + zi * sCi;
    __half* Ch = (__half*)Cv + coff;
    float*  Cf = (float*)Cv + coff;

    extern __shared__ __align__(16) char smem_raw[];
    const unsigned asb = (unsigned)__cvta_generic_to_shared(smem_raw);
    const unsigned bsb = asb + (unsigned)(STAGES * AH_ST * 2);

    const int tid  = threadIdx.x;
    const int lane = tid & 31;
    const int warp = tid >> 5;
    const int wm   = (warp & 1) * 64;
    const int wn   = (warp >> 1) * 64;
    const int g    = lane >> 2;
    const int t    = lane & 3;

    const int lp = lane >> 3;
    const int lr = lane & 7;
    const int aRowOff  = (lp & 1) * 8 + lr;
    const int aColOff  = (lp >> 1) * 8;
    const int bRowOff  = (lp >> 1) * 8 + lr;
    const int bColOff  = (lp & 1) * 8;
    const int ntRowOff = (lp & 1) * 8 + lr;
    const int ntColOff = (lp >> 1) * 8;

    float acc[4][8][4];
    #pragma unroll
    for (int i = 0; i < 4; i++)
        #pragma unroll
        for (int j = 0; j < 8; j++)
            #pragma unroll
            for (int r = 0; r < 4; r++) acc[i][j][r] = 0.f;

    auto issue = [&](int s, int k0) {
        const unsigned aB = asb + (unsigned)(s * AH_ST * 2);
        #pragma unroll
        for (int h = 0; h < 4; h++) {
            int row = (tid >> 2) + 32 * h;
            cp_async16(aB + (unsigned)((row * AL + (tid & 3) * 8) * 2),
                       &A[(long long)(bm + row) * lda + k0 + (tid & 3) * 8]);
        }
        const unsigned bB = bsb + (unsigned)(s * BH_ST * 2);
        if (TRANSB) {
            #pragma unroll
            for (int h = 0; h < 4; h++) {
                int row = (tid >> 2) + 32 * h;
                cp_async16(bB + (unsigned)((row * AL + (tid & 3) * 8) * 2),
                           &Bg[(long long)(bn + row) * ldb + k0 + (tid & 3) * 8]);
            }
        } else {
            #pragma unroll
            for (int h = 0; h < 4; h++) {
                int idx = h * 128 + tid;
                int kr  = idx >> 4;
                int ch  = idx & 15;
                cp_async16(bB + (unsigned)((kr * BLN + ch * 8) * 2),
                           &Bg[(long long)(k0 + kr) * ldb + bn + ch * 8]);
            }
        }
    };

    auto compute = [&](int p) {
        const unsigned abase = asb + (unsigned)(p * AH_ST * 2)
                             + (unsigned)(((wm + aRowOff) * AL + aColOff) * 2);
        unsigned bbase;
        if (TRANSB)
            bbase = bsb + (unsigned)(p * BH_ST * 2)
                  + (unsigned)(((wn + bRowOff) * AL + bColOff) * 2);
        else
            bbase = bsb + (unsigned)(p * BH_ST * 2)
                  + (unsigned)((ntRowOff * BLN + wn + ntColOff) * 2);
        #pragma unroll
        for (int ks = 0; ks < 2; ks++) {
            const int kk = ks * 16;
            unsigned af[4][4], bf[8][2];
            #pragma unroll
            for (int i = 0; i < 4; i++)
                ldsm4(af[i][0], af[i][1], af[i][2], af[i][3],
                      abase + (unsigned)((i * 16 * AL + kk) * 2));
            if (TRANSB) {
                #pragma unroll
                for (int jp = 0; jp < 4; jp++) {
                    unsigned r0, r1, r2, r3;
                    ldsm4(r0, r1, r2, r3, bbase + (unsigned)((jp * 16 * AL + kk) * 2));
                    bf[2 * jp][0] = r0; bf[2 * jp][1] = r1;
                    bf[2 * jp + 1][0] = r2; bf[2 * jp + 1][1] = r3;
                }
            } else {
                #pragma unroll
                for (int jp = 0; jp < 4; jp++) {
                    unsigned r0, r1, r2, r3;
                    ldsm4t(r0, r1, r2, r3,
                           bbase + (unsigned)((kk * BLN + jp * 16) * 2));
                    bf[2 * jp][0] = r0; bf[2 * jp][1] = r1;
                    bf[2 * jp + 1][0] = r2; bf[2 * jp + 1][1] = r3;
                }
            }
            #pragma unroll
            for (int i = 0; i < 4; i++)
                #pragma unroll
                for (int j = 0; j < 8; j++)
                    mma_f16(acc[i][j], af[i], bf[j]);
        }
    };

    const int nk = Keff / BKH;
    #pragma unroll
    for (int s = 0; s < STAGES - 1; s++) {
        if (s < nk) issue(s, s * BKH);
        CP_COMMIT();
    }
    for (int kt = 0; kt < nk; kt++) {
        CP_WAIT2();
        __syncthreads();
        compute(kt % STAGES);
        if (kt + STAGES - 1 < nk)
            issue((kt + STAGES - 1) % STAGES, (kt + STAGES - 1) * BKH);
        CP_COMMIT();
    }

    #pragma unroll
    for (int i = 0; i < 4; i++) {
        #pragma unroll
        for (int j = 0; j < 8; j++) {
            const long long row = bm + wm + i * 16 + g;
            const int       col = bn + wn + j * 8 + 2 * t;
            float2 v0 = make_float2(acc[i][j][0] * alpha, acc[i][j][1] * alpha);
            float2 v1 = make_float2(acc[i][j][2] * alpha, acc[i][j][3] * alpha);
            if (EPI == 2) {
                const float c = 0.70710678118654752f;
                v0.x = 0.5f * v0.x * erfcf(-v0.x * c);
                v0.y = 0.5f * v0.y * erfcf(-v0.y * c);
                v1.x = 0.5f * v1.x * erfcf(-v1.x * c);
                v1.y = 0.5f * v1.y * erfcf(-v1.y * c);
            }
            if (OUTHALF) {
                *(__half2*)&Ch[row * (long long)ldc + col]       = __floats2half2_rn(v0.x, v0.y);
                *(__half2*)&Ch[(row + 8) * (long long)ldc + col] = __floats2half2_rn(v1.x, v1.y);
            } else {
                *(float2*)&Cf[row * (long long)ldc + col]       = v0;
                *(float2*)&Cf[(row + 8) * (long long)ldc + col] = v1;
            }
        }
    }
}

// ---------------------------------------------------------------- flash v2: 2-pass, no P materialization
constexpr int FL_STRIDE = 136;                       // halves
constexpr int FL_TILE   = 128 * FL_STRIDE * 2;       // 34816 B
constexpr int FL_CS     = 8 * 128 * 4;               // 4096 B warp colsum buffer
constexpr int FL_SMEM   = 4 * FL_TILE + FL_CS;       // 143360 B

__global__ __launch_bounds__(256, 1) void flash2_k(
    const __half* __restrict__ qkv, float* __restrict__ part2,
    __half* __restrict__ y, float scale2)
{
    const int qb = blockIdx.x;
    const int bh = blockIdx.y;
    const int b  = bh >> 3;
    const int h  = bh & 7;
    const int D3 = 3 * Dd;

    const __half* Qp = qkv + ((long long)(b * Ss + qb * 128)) * D3 + h * HD;
    const __half* Kp = qkv + ((long long)b * Ss) * D3 + Dd + h * HD;
    const __half* Vp = qkv + ((long long)b * Ss) * D3 + 2 * Dd + h * HD;
    __half* yp = y + ((long long)(b * Ss + qb * 128)) * Dd + h * HD;
    float* p2p = part2 + ((size_t)bh * 8 + qb) * 1024;

    extern __shared__ __align__(16) char smemraw[];
    const unsigned sb = (unsigned)__cvta_generic_to_shared(smemraw);
    const unsigned kB0 = sb, kB1 = sb + FL_TILE;
    const unsigned vB0 = sb + 2 * FL_TILE, vB1 = sb + 3 * FL_TILE;
    float* sm_cs = (float*)(smemraw + 4 * FL_TILE);

    const int tid  = threadIdx.x;
    const int lane = tid & 31;
    const int warp = tid >> 5;
    const int wq   = warp * 16;
    const int g    = lane >> 2;
    const int t    = lane & 3;
    const int lp = lane >> 3, lr = lane & 7;
    const int aRowOff  = (lp & 1) * 8 + lr;
    const int aColOff  = (lp >> 1) * 8;
    const int bRowOff  = (lp >> 1) * 8 + lr;
    const int bColOff  = (lp & 1) * 8;
    const int ntRowOff = (lp & 1) * 8 + lr;
    const int ntColOff = (lp >> 1) * 8;

    auto loadTile = [&](unsigned dstB, const __half* src) {
        #pragma unroll
        for (int i2 = 0; i2 < 8; i2++) {
            int idx = i2 * 256 + tid;
            int r = idx >> 4, ch = idx & 15;
            cp_async16(dstB + (unsigned)((r * FL_STRIDE + ch * 8) * 2),
                       src + (long long)r * D3 + ch * 8);
        }
    };

    loadTile(vB0, Qp); CP_COMMIT();
    loadTile(kB0, Kp); CP_COMMIT();
    CP_WAIT1();
    __syncthreads();
    unsigned aQ[8][4];
    {
        const unsigned abase = vB0 + (unsigned)(((wq + aRowOff) * FL_STRIDE + aColOff) * 2);
        #pragma unroll
        for (int ks = 0; ks < 8; ks++)
            ldsm4(aQ[ks][0], aQ[ks][1], aQ[ks][2], aQ[ks][3],
                  abase + (unsigned)(ks * 32));
    }

    const int rloc0 = wq + g, rloc1 = rloc0 + 8;
    float m0 = -1e30f, m1 = -1e30f, l0 = 0.f, l1 = 0.f;

    auto computeS = [&](unsigned kbuf, float (*ct)[4], bool diag) {
        #pragma unroll
        for (int nt = 0; nt < 16; nt++) {
            ct[nt][0] = 0.f; ct[nt][1] = 0.f; ct[nt][2] = 0.f; ct[nt][3] = 0.f;
        }
        const unsigned bbase = kbuf + (unsigned)((bRowOff * FL_STRIDE + bColOff) * 2);
        #pragma unroll
        for (int ks = 0; ks < 8; ks++) {
            unsigned bf[16][2];
            #pragma unroll
            for (int jp = 0; jp < 8; jp++) {
                unsigned r0, r1, r2, r3;
                ldsm4(r0, r1, r2, r3,
                      bbase + (unsigned)((jp * 16 * FL_STRIDE + ks * 16) * 2));
                bf[2 * jp][0] = r0; bf[2 * jp][1] = r1;
                bf[2 * jp + 1][0] = r2; bf[2 * jp + 1][1] = r3;
            }
            #pragma unroll
            for (int nt = 0; nt < 16; nt++)
                mma_f16(ct[nt], aQ[ks], bf[nt]);
        }
        #pragma unroll
        for (int nt = 0; nt < 16; nt++) {
            #pragma unroll
            for (int e = 0; e < 2; e++) {
                float s0 = ct[nt][e]     * scale2;
                float s1 = ct[nt][2 + e] * scale2;
                if (diag) {
                    int col = nt * 8 + 2 * t + e;
                    if (col > rloc0) s0 = -1e30f;
                    if (col > rloc1) s1 = -1e30f;
                }
                ct[nt][e] = s0; ct[nt][2 + e] = s1;
            }
        }
    };

    // pass 1: softmax stats
    for (int kb = 0; kb <= qb; kb++) {
        const int cur = kb & 1;
        if (kb < qb) loadTile(cur ? kB0 : kB1, Kp + (long long)(kb + 1) * 128 * D3);
        CP_COMMIT();
        CP_WAIT1();
        __syncthreads();

        float ct[16][4];
        computeS(cur ? kB1 : kB0, ct, kb == qb);

        float mx0 = -1e30f, mx1 = -1e30f;
        #pragma unroll
        for (int nt = 0; nt < 16; nt++) {
            mx0 = fmaxf(mx0, fmaxf(ct[nt][0], ct[nt][1]));
            mx1 = fmaxf(mx1, fmaxf(ct[nt][2], ct[nt][3]));
        }
        mx0 = fmaxf(mx0, __shfl_xor_sync(0xffffffffu, mx0, 1));
        mx0 = fmaxf(mx0, __shfl_xor_sync(0xffffffffu, mx0, 2));
        mx1 = fmaxf(mx1, __shfl_xor_sync(0xffffffffu, mx1, 1));
        mx1 = fmaxf(mx1, __shfl_xor_sync(0xffffffffu, mx1, 2));
        const float m0n = fmaxf(m0, mx0), m1n = fmaxf(m1, mx1);
        const float f0 = exp2f(m0 - m0n), f1 = exp2f(m1 - m1n);
        float rs0 = 0.f, rs1 = 0.f;
        #pragma unroll
        for (int nt = 0; nt < 16; nt++) {
            rs0 += exp2f(ct[nt][0] - m0n) + exp2f(ct[nt][1] - m0n);
            rs1 += exp2f(ct[nt][2] - m1n) + exp2f(ct[nt][3] - m1n);
        }
        rs0 += __shfl_xor_sync(0xffffffffu, rs0, 1);
        rs0 += __shfl_xor_sync(0xffffffffu, rs0, 2);
        rs1 += __shfl_xor_sync(0xffffffffu, rs1, 1);
        rs1 += __shfl_xor_sync(0xffffffffu, rs1, 2);
        l0 = l0 * f0 + rs0;
        l1 = l1 * f1 + rs1;
        m0 = m0n; m1 = m1n;
        __syncthreads();
    }
    const float inv0 = 1.f / l0, inv1 = 1.f / l1;

    // pass 2: P, O, column sums
    float oc[16][4];
    #pragma unroll
    for (int nt = 0; nt < 16; nt++) {
        oc[nt][0] = 0.f; oc[nt][1] = 0.f; oc[nt][2] = 0.f; oc[nt][3] = 0.f;
    }
    loadTile(kB0, Kp); loadTile(vB0, Vp); CP_COMMIT();
    for (int kb = 0; kb <= qb; kb++) {
        const int cur = kb & 1;
        if (kb < qb) {
            loadTile(cur ? kB0 : kB1, Kp + (long long)(kb + 1) * 128 * D3);
            loadTile(cur ? vB0 : vB1, Vp + (long long)(kb + 1) * 128 * D3);
        }
        CP_COMMIT();
        CP_WAIT1();
        __syncthreads();

        float ct[16][4];
        computeS(cur ? kB1 : kB0, ct, kb == qb);
        #pragma unroll
        for (int nt = 0; nt < 16; nt++) {
            ct[nt][0] = exp2f(ct[nt][0] - m0) * inv0;
            ct[nt][1] = exp2f(ct[nt][1] - m0) * inv0;
            ct[nt][2] = exp2f(ct[nt][2] - m1) * inv1;
            ct[nt][3] = exp2f(ct[nt][3] - m1) * inv1;
        }

        #pragma unroll
        for (int nt = 0; nt < 16; nt++) {
            float c0 = ct[nt][0] + ct[nt][2];
            float c1 = ct[nt][1] + ct[nt][3];
            c0 += __shfl_xor_sync(0xffffffffu, c0, 4);
            c0 += __shfl_xor_sync(0xffffffffu, c0, 8);
            c0 += __shfl_xor_sync(0xffffffffu, c0, 16);
            c1 += __shfl_xor_sync(0xffffffffu, c1, 4);
            c1 += __shfl_xor_sync(0xffffffffu, c1, 8);
            c1 += __shfl_xor_sync(0xffffffffu, c1, 16);
            if (lane < 4) {
                sm_cs[warp * 128 + nt * 8 + 2 * t]     = c0;
                sm_cs[warp * 128 + nt * 8 + 2 * t + 1] = c1;
            }
        }

        {
            const unsigned vbase = (cur ? vB1 : vB0)
                                 + (unsigned)((ntRowOff * FL_STRIDE + ntColOff) * 2);
            #pragma unroll
            for (int ks = 0; ks < 8; ks++) {
                unsigned aP[4];
                aP[0] = h2u(ct[2 * ks][0],     ct[2 * ks][1]);
                aP[1] = h2u(ct[2 * ks][2],     ct[2 * ks][3]);
                aP[2] = h2u(ct[2 * ks + 1][0], ct[2 * ks + 1][1]);
                aP[3] = h2u(ct[2 * ks + 1][2], ct[2 * ks + 1][3]);
                unsigned bf[16][2];
                #pragma unroll
                for (int jp = 0; jp < 8; jp++) {
                    unsigned r0, r1, r2, r3;
                    ldsm4t(r0, r1, r2, r3,
                           vbase + (unsigned)((ks * 16 * FL_STRIDE + jp * 16) * 2));
                    bf[2 * jp][0] = r0; bf[2 * jp][1] = r1;
                    bf[2 * jp + 1][0] = r2; bf[2 * jp + 1][1] = r3;
                }
                #pragma unroll
                for (int nt = 0; nt < 16; nt++)
                    mma_f16(oc[nt], aP, bf[nt]);
            }
        }
        __syncthreads();
        if (tid < 128) {
            float s = 0.f;
            #pragma unroll
            for (int w = 0; w < 8; w++) s += sm_cs[w * 128 + tid];
            p2p[kb * 128 + tid] = s;
        }
        __syncthreads();
    }

    __half2* y0 = (__half2*)(yp + (long long)rloc0 * Dd + 2 * t);
    __half2* y1 = (__half2*)(yp + (long long)rloc1 * Dd + 2 * t);
    #pragma unroll
    for (int nt = 0; nt < 16; nt++) {
        y0[nt * 4] = __floats2half2_rn(oc[nt][0], oc[nt][1]);
        y1[nt * 4] = __floats2half2_rn(oc[nt][2], oc[nt][3]);
    }
}

// ---------------------------------------------------------------- amap accumulate (fixed order)
__global__ __launch_bounds__(256) void amap_k(
    const float* __restrict__ part2, float* __restrict__ amap)
{
    const int i = blockIdx.x * 256 + threadIdx.x;   // 0..2047
    const int b = i >> 10, k = i & 1023;
    const int qb0 = k >> 7;
    float s = 0.f;
    for (int h = 0; h < Hh; h++)
        for (int qb = qb0; qb < 8; qb++)
            s += part2[(((size_t)(b * Hh + h)) * 8 + qb) * 1024 + k];
    amap[i] += s;
}

// ---------------------------------------------------------------- fused split-K reduce (+bias)(+snapshot)(+LN -> half xn)
template<int P, bool BIAS, bool SNAP, bool OUTLN>
__global__ __launch_bounds__(256) void reduce_ln_k(
    const float4* __restrict__ part, float4* __restrict__ x,
    const float* __restrict__ bias, float4* __restrict__ st, int layer,
    const float* __restrict__ g, const float* __restrict__ b,
    __half* __restrict__ xn)
{
    __shared__ float sm0[8], sm1[8];
    const int row = blockIdx.x, tid = threadIdx.x;
    const int i = row * 256 + tid;
    constexpr int N4 = BS * Dd / 4;

    float4 s = part[i];
    #pragma unroll
    for (int p = 1; p < P; p++) {
        float4 v = part[(size_t)p * N4 + i];
        s.x += v.x; s.y += v.y; s.z += v.z; s.w += v.w;
    }
    if (BIAS) {
        float4 bb = ((const float4*)bias)[tid];
        s.x += bb.x; s.y += bb.y; s.z += bb.z; s.w += bb.w;
    }
    float4 v = x[i];
    v.x += s.x; v.y += s.y; v.z += s.z; v.w += s.w;
    x[i] = v;
    if (SNAP)
        st[((long long)row * DEPTH + layer) * 256 + tid] = v;

    if (OUTLN) {
        float su  = v.x + v.y + v.z + v.w;
        float su2 = v.x * v.x + v.y * v.y + v.z * v.z + v.w * v.w;
        #pragma unroll
        for (int o = 16; o > 0; o >>= 1) {
            su  += __shfl_xor_sync(0xffffffffu, su,  o);
            su2 += __shfl_xor_sync(0xffffffffu, su2, o);
        }
        if ((tid & 31) == 0) { sm0[tid >> 5] = su; sm1[tid >> 5] = su2; }
        __syncthreads();
        if (tid < 32) {
            su  = (tid < 8) ? sm0[tid] : 0.f;
            su2 = (tid < 8) ? sm1[tid] : 0.f;
            #pragma unroll
            for (int o = 4; o > 0; o >>= 1) {
                su  += __shfl_xor_sync(0xffffffffu, su,  o);
                su2 += __shfl_xor_sync(0xffffffffu, su2, o);
            }
            if (tid == 0) { sm0[0] = su; sm1[0] = su2; }
        }
        __syncthreads();
        const float mean = sm0[0] * (1.f / Dd);
        const float var  = sm1[0] * (1.f / Dd) - mean * mean;
        const float rstd = rsqrtf(var + 1e-5f);
        float4 gg = ((const float4*)g)[tid];
        float4 bb = ((const float4*)b)[tid];
        float4 o;
        o.x = (v.x - mean) * rstd * gg.x + bb.x;
        o.y = (v.y - mean) * rstd * gg.y + bb.y;
        o.z = (v.z - mean) * rstd * gg.z + bb.z;
        o.w = (v.w - mean) * rstd * gg.w + bb.w;
        __half2* oh = (__half2*)(xn + (long long)row * Dd);
        oh[2 * tid]     = __floats2half2_rn(o.x, o.y);
        oh[2 * tid + 1] = __floats2half2_rn(o.z, o.w);
    }
}

// ---------------------------------------------------------------- transpose + cvt to half (half2-packed writes)
// dst[c][r] = half(src[r][c]); tile 64 src-rows x 32 src-cols
__global__ __launch_bounds__(256) void transpose_cvt_k(
    const float* __restrict__ src, __half* __restrict__ dst,
    int R, int C, long long sSrc, long long sDst)
{
    __shared__ float tile[64][33];
    src += blockIdx.z * sSrc;
    dst += blockIdx.z * sDst;
    const int c0 = blockIdx.x * 32, r0 = blockIdx.y * 64;
    const int tid = threadIdx.x;
    #pragma unroll
    for (int it = 0; it < 8; it++) {
        int idx = it * 256 + tid;
        int r = idx >> 5, c = idx & 31;
        tile[r][c] = src[(long long)(r0 + r) * C + c0 + c];
    }
    __syncthreads();
    #pragma unroll
    for (int it = 0; it < 4; it++) {
        int idx = it * 256 + tid;
        int c = idx >> 5, j = idx & 31;
        __half2 h = __floats2half2_rn(tile[2 * j][c], tile[2 * j + 1][c]);
        *((__half2*)(dst + (long long)(c0 + c) * R + r0) + j) = h;
    }
}

// ---------------------------------------------------------------- LayerNorm (standalone)
template<bool OUTH>
__global__ __launch_bounds__(256) void ln_k(
    const float* __restrict__ x, const float* __restrict__ g,
    const float* __restrict__ b, void* __restrict__ outv)
{
    __shared__ float sm0[8], sm1[8];
    const int row = blockIdx.x, tid = threadIdx.x;
    float4 v = ((const float4*)(x + (long long)row * Dd))[tid];
    float s  = v.x + v.y + v.z + v.w;
    float s2 = v.x * v.x + v.y * v.y + v.z * v.z + v.w * v.w;
    #pragma unroll
    for (int o = 16; o > 0; o >>= 1) {
        s  += __shfl_xor_sync(0xffffffffu, s,  o);
        s2 += __shfl_xor_sync(0xffffffffu, s2, o);
    }
    if ((tid & 31) == 0) { sm0[tid >> 5] = s; sm1[tid >> 5] = s2; }
    __syncthreads();
    if (tid < 32) {
        s  = (tid < 8) ? sm0[tid] : 0.f;
        s2 = (tid < 8) ? sm1[tid] : 0.f;
        #pragma unroll
        for (int o = 4; o > 0; o >>= 1) {
            s  += __shfl_xor_sync(0xffffffffu, s,  o);
            s2 += __shfl_xor_sync(0xffffffffu, s2, o);
        }
        if (tid == 0) { sm0[0] = s; sm1[0] = s2; }
    }
    __syncthreads();
    const float mean = sm0[0] * (1.f / Dd);
    const float var  = sm1[0] * (1.f / Dd) - mean * mean;
    const float rstd = rsqrtf(var + 1e-5f);
    float4 gg = ((const float4*)g)[tid];
    float4 bb = ((const float4*)b)[tid];
    float4 o;
    o.x = (v.x - mean) * rstd * gg.x + bb.x;
    o.y = (v.y - mean) * rstd * gg.y + bb.y;
    o.z = (v.z - mean) * rstd * gg.z + bb.z;
    o.w = (v.w - mean) * rstd * gg.w + bb.w;
    if (OUTH) {
        __half2* oh = (__half2*)((__half*)outv + (long long)row * Dd);
        oh[2 * tid]     = __floats2half2_rn(o.x, o.y);
        oh[2 * tid + 1] = __floats2half2_rn(o.z, o.w);
    } else {
        ((float4*)((float*)outv + (long long)row * Dd))[tid] = o;
    }
}

// ---------------------------------------------------------------- misc
__global__ __launch_bounds__(256) void init_x_snap_k(
    const float4* __restrict__ token, float4* __restrict__ x,
    float4* __restrict__ st)
{
    const int i = blockIdx.x * 256 + threadIdx.x;
    float4 v = token[i];
    x[i] = v;
    st[((long long)(i >> 8) * DEPTH + 0) * 256 + (i & 255)] = v;
}

__global__ void zero_k(float* p, int n)
{
    int i = blockIdx.x * 256 + threadIdx.x;
    if (i < n) p[i] = 0.f;
}

// ---------------------------------------------------------------- launcher
extern "C" void kernel_launch(void* const* d_in, const int* in_sizes, int n_in,
                              void* d_out, int out_size)
{
    const float* token = (const float*)d_in[0];
    const float* Wq    = (const float*)d_in[1];
    const float* Wkv   = (const float*)d_in[2];
    const float* Wo    = (const float*)d_in[3];
    const float* b_o   = (const float*)d_in[4];
    const float* g1    = (const float*)d_in[5];
    const float* b1    = (const float*)d_in[6];
    const float* g3    = (const float*)d_in[7];
    const float* b3    = (const float*)d_in[8];
    const float* W1    = (const float*)d_in[9];
    const float* W2    = (const float*)d_in[10];
    const float* gout  = (const float*)d_in[11];
    const float* bout  = (const float*)d_in[12];
    float* out = (float*)d_out;

    float *x, *red, *part2;
    __half *xn, *qkv, *wqkvT, *woT, *w1T, *w2T, *y, *ff;
    cudaGetSymbolAddress((void**)&x,     g_x);
    cudaGetSymbolAddress((void**)&xn,    g_xn);
    cudaGetSymbolAddress((void**)&qkv,   g_qkv);
    cudaGetSymbolAddress((void**)&wqkvT, g_wqkvT);
    cudaGetSymbolAddress((void**)&woT,   g_woT);
    cudaGetSymbolAddress((void**)&w1T,   g_w1T);
    cudaGetSymbolAddress((void**)&w2T,   g_w2T);
    cudaGetSymbolAddress((void**)&part2, g_part2);
    cudaGetSymbolAddress((void**)&y,     g_y);
    cudaGetSymbolAddress((void**)&ff,    g_ff);
    cudaGetSymbolAddress((void**)&red,   g_red);

    cudaFuncSetAttribute(gemm_h<0, true,  true >, cudaFuncAttributeMaxDynamicSharedMemorySize, GEMM_SMEM);
    cudaFuncSetAttribute(gemm_h<0, true,  false>, cudaFuncAttributeMaxDynamicSharedMemorySize, GEMM_SMEM);
    cudaFuncSetAttribute(gemm_h<2, true,  true >, cudaFuncAttributeMaxDynamicSharedMemorySize, GEMM_SMEM);
    cudaFuncSetAttribute(flash2_k, cudaFuncAttributeMaxDynamicSharedMemorySize, FL_SMEM);

    float* out_state = out + (size_t)BS * Dd;
    float* amap      = out_state + (size_t)BS * DEPTH * Dd;

    init_x_snap_k<<<BS * Dd / 4 / 256, 256>>>((const float4*)token, (float4*)x,
                                              (float4*)out_state);
    zero_k<<<(BS + 255) / 256, 256>>>(amap, BS);

    const int D3 = 3 * Dd;
    transpose_cvt_k<<<dim3(Dd / 32, Dd / 64, DEPTH), 256>>>(
        Wq, wqkvT, Dd, Dd, (long long)Dd * Dd, (long long)D3 * Dd);
    transpose_cvt_k<<<dim3(2 * Dd / 32, Dd / 64, DEPTH), 256>>>(
        Wkv, wqkvT + (size_t)Dd * Dd, Dd, 2 * Dd,
        (long long)Dd * 2 * Dd, (long long)D3 * Dd);
    transpose_cvt_k<<<dim3(Dd / 32, Dd / 64, DEPTH), 256>>>(
        Wo, woT, Dd, Dd, (long long)Dd * Dd, (long long)Dd * Dd);
    transpose_cvt_k<<<dim3(FF / 32, Dd / 64, DEPTH), 256>>>(
        W1, w1T, Dd, FF, (long long)Dd * FF, (long long)Dd * FF);
    transpose_cvt_k<<<dim3(Dd / 32, FF / 64, DEPTH), 256>>>(
        W2, w2T, FF, Dd, (long long)FF * Dd, (long long)FF * Dd);

    const float scale2 = rsqrtf((float)HD) * 1.4426950408889634f;   // scale * log2(e)

    // layer-0 LN1
    ln_k<true><<<BS, 256>>>(x, g1, b1, xn);

    for (int l = 0; l < DEPTH; l++) {
        // QKV = xn @ [Wq|Wkv]^T
        gemm_h<0, true, true><<<dim3(D3 / BN, BS / BM, 1), 128, GEMM_SMEM>>>(
            xn, wqkvT + (size_t)l * D3 * Dd, qkv,
            Dd, Dd, Dd, D3, 0, 0, 0, 0, 0, 0, 1, 1.f, 0);
        // fused attention: scores + softmax + colsum + A@V, no P materialization
        flash2_k<<<dim3(8, Bb * Hh), 256, FL_SMEM>>>(qkv, part2, y, scale2);
        // amap += column sums
        amap_k<<<Bb * Ss / 256, 256>>>(part2, amap);
        // Wo GEMM (split-K=2, fp32 partials)
        gemm_h<0, true, false><<<dim3(Dd / BN, BS / BM, 2), 128, GEMM_SMEM>>>(
            y, woT + (size_t)l * Dd * Dd, red,
            Dd / 2, Dd, Dd, Dd,
            0, Dd / 2, 0, Dd / 2,
            0, (long long)BS * Dd,
            2, 1.f, 0);
        reduce_ln_k<2, true, false, true><<<BS, 256>>>(
            (const float4*)red, (float4*)x, b_o + l * Dd, nullptr, 0,
            g3 + l * Dd, b3 + l * Dd, xn);
        // ff = gelu(xn @ W1^T)
        gemm_h<2, true, true><<<dim3(FF / BN, BS / BM, 1), 128, GEMM_SMEM>>>(
            xn, w1T + (size_t)l * FF * Dd, ff,
            Dd, Dd, Dd, FF, 0, 0, 0, 0, 0, 0, 1, 1.f, 0);
        // FF2 GEMM (split-K=4)
        gemm_h<0, true, false><<<dim3(Dd / BN, BS / BM, 4), 128, GEMM_SMEM>>>(
            ff, w2T + (size_t)l * Dd * FF, red,
            FF / 4, FF, FF, Dd,
            0, FF / 4, 0, FF / 4,
            0, (long long)BS * Dd,
            4, 1.f, 0);
        if (l < DEPTH - 1)
            reduce_ln_k<4, false, true, true><<<BS, 256>>>(
                (const float4*)red, (float4*)x, nullptr, (float4*)out_state, l + 1,
                g1 + (l + 1) * Dd, b1 + (l + 1) * Dd, xn);
        else
            reduce_ln_k<4, false, false, false><<<BS, 256>>>(
                (const float4*)red, (float4*)x, nullptr, nullptr, 0,
                nullptr, nullptr, nullptr);
    }
    // final LN -> x_out (fp32)
    ln_k<false><<<BS, 256>>>(x, gout, bout, out);
}

// round 16
// speedup vs baseline: 1.0998x; 1.0738x over previous
#include <cuda_runtime.h>
#include <cuda_fp16.h>
#include <math.h>
#include <stdint.h>

// Problem constants
constexpr int Bb    = 2;
constexpr int Ss    = 1024;
constexpr int Dd    = 1024;
constexpr int Hh    = 8;
constexpr int HD    = 128;
constexpr int DEPTH = 8;
constexpr int FF    = 4096;
constexpr int BS    = Bb * Ss;      // 2048

// Scratch (device globals: allocation-free)
__device__ float  g_x  [BS * Dd];
__device__ __half g_xn [BS * Dd];
__device__ __half g_qkv[(size_t)BS * 3 * Dd];            // q | k | v packed (half)
__device__ __half g_wqkvT[(size_t)DEPTH * 3 * Dd * Dd];  // [Wq|Wkv]^T [3D][D] half
__device__ __half g_woT [(size_t)DEPTH * Dd * Dd];       // Wo^T  [D][D] half
__device__ __half g_w1T [(size_t)DEPTH * FF * Dd];       // W1^T  [FF][D] half
__device__ __half g_w2T [(size_t)DEPTH * Dd * FF];       // W2^T  [D][FF] half
__device__ float  g_part2[(size_t)Bb * Hh * 8 * 1024];   // per (bh, qb) column sums
__device__ __half g_y  [BS * Dd];
__device__ __half g_ff [(size_t)BS * FF];
__device__ float  g_red[(size_t)4 * BS * Dd];            // split-K partials (fp32)

// ---------------------------------------------------------------- mma / ldmatrix
__device__ __forceinline__ void mma_f16(float* c, const unsigned* a, const unsigned* b) {
    asm volatile(
        "mma.sync.aligned.m16n8k16.row.col.f32.f16.f16.f32 "
        "{%0,%1,%2,%3}, {%4,%5,%6,%7}, {%8,%9}, {%0,%1,%2,%3};"
        : "+f"(c[0]), "+f"(c[1]), "+f"(c[2]), "+f"(c[3])
        : "r"(a[0]), "r"(a[1]), "r"(a[2]), "r"(a[3]), "r"(b[0]), "r"(b[1]));
}
__device__ __forceinline__ void ldsm4(unsigned& r0, unsigned& r1, unsigned& r2,
                                      unsigned& r3, unsigned addr) {
    asm volatile("ldmatrix.sync.aligned.m8n8.x4.shared.b16 {%0,%1,%2,%3}, [%4];"
                 : "=r"(r0), "=r"(r1), "=r"(r2), "=r"(r3) : "r"(addr));
}
__device__ __forceinline__ void ldsm4t(unsigned& r0, unsigned& r1, unsigned& r2,
                                       unsigned& r3, unsigned addr) {
    asm volatile("ldmatrix.sync.aligned.m8n8.x4.trans.shared.b16 {%0,%1,%2,%3}, [%4];"
                 : "=r"(r0), "=r"(r1), "=r"(r2), "=r"(r3) : "r"(addr));
}
__device__ __forceinline__ void cp_async16(unsigned saddr, const void* gptr) {
    asm volatile("cp.async.cg.shared.global [%0], [%1], 16;"
                 :: "r"(saddr), "l"(gptr));
}
#define CP_COMMIT() asm volatile("cp.async.commit_group;")
#define CP_WAIT1()  asm volatile("cp.async.wait_group 1;")

__device__ __forceinline__ unsigned h2u(float a, float b) {
    __half2 h = __floats2half2_rn(a, b);
    return *(unsigned*)&h;
}

// ---------------------------------------------------------------- fp16 tensor-core GEMM (weights, all B^T [N][K])
// C[M,N] = epi(alpha * A[M,K] @ B^T). BKH=64 k-tiles, 3 stages, 2 CTAs/SM.
#define BM 128
#define BN 128
#define BKH 64          // halves per k-tile
#define AL 72           // row length in halves: 144B rows, 16B-aligned, conflict-free ldsm
#define STAGES 3
constexpr int OP_ST = BM * AL;                              // 9216 halves per operand stage
constexpr int GEMM_SMEM = STAGES * 2 * OP_ST * 2;           // 110592 B

template<int EPI, bool OUTHALF>
__global__ __launch_bounds__(128, 2) void gemm_h(
    const __half* __restrict__ A, const __half* __restrict__ Bg,
    void* __restrict__ Cv,
    int K, int lda, int ldb, int ldc,
    long long sAi, long long sBi, long long sCi,
    float alpha)
{
    const int bm = blockIdx.y * BM;
    const int bn = blockIdx.x * BN;
    const long long zi = blockIdx.z;
    A  += zi * sAi;
    Bg += zi * sBi;
    const long long coff = zi * sCi;
    __half* Ch = (__half*)Cv + coff;
    float*  Cf = (float*)Cv + coff;

    extern __shared__ __align__(16) char smem_raw[];
    const unsigned asb = (unsigned)__cvta_generic_to_shared(smem_raw);
    const unsigned bsb = asb + (unsigned)(STAGES * OP_ST * 2);

    const int tid  = threadIdx.x;
    const int lane = tid & 31;
    const int warp = tid >> 5;
    const int wm   = (warp & 1) * 64;
    const int wn   = (warp >> 1) * 64;
    const int g    = lane >> 2;
    const int t    = lane & 3;

    const int lp = lane >> 3;
    const int lr = lane & 7;
    const int aRowOff = (lp & 1) * 8 + lr;
    const int aColOff = (lp >> 1) * 8;
    const int bRowOff = (lp >> 1) * 8 + lr;
    const int bColOff = (lp & 1) * 8;

    float acc[4][8][4];
    #pragma unroll
    for (int i = 0; i < 4; i++)
        #pragma unroll
        for (int j = 0; j < 8; j++)
            #pragma unroll
            for (int r = 0; r < 4; r++) acc[i][j][r] = 0.f;

    // 1024 16B-chunks per operand per tile: 8 per thread
    auto issue = [&](int s, int k0) {
        const unsigned aB = asb + (unsigned)(s * OP_ST * 2);
        const unsigned bB = bsb + (unsigned)(s * OP_ST * 2);
        #pragma unroll
        for (int h = 0; h < 8; h++) {
            int idx = h * 128 + tid;
            int row = idx >> 3, ch = idx & 7;        // 8 chunks x 16B = 64 halves/row
            cp_async16(aB + (unsigned)((row * AL + ch * 8) * 2),
                       &A[(long long)(bm + row) * lda + k0 + ch * 8]);
            cp_async16(bB + (unsigned)((row * AL + ch * 8) * 2),
                       &Bg[(long long)(bn + row) * ldb + k0 + ch * 8]);
        }
    };

    auto compute = [&](int p) {
        const unsigned abase = asb + (unsigned)(p * OP_ST * 2)
                             + (unsigned)(((wm + aRowOff) * AL + aColOff) * 2);
        const unsigned bbase = bsb + (unsigned)(p * OP_ST * 2)
                             + (unsigned)(((wn + bRowOff) * AL + bColOff) * 2);
        #pragma unroll
        for (int ks = 0; ks < 4; ks++) {
            const int kk = ks * 16;
            unsigned af[4][4], bf[8][2];
            #pragma unroll
            for (int i = 0; i < 4; i++)
                ldsm4(af[i][0], af[i][1], af[i][2], af[i][3],
                      abase + (unsigned)((i * 16 * AL + kk) * 2));
            #pragma unroll
            for (int jp = 0; jp < 4; jp++) {
                unsigned r0, r1, r2, r3;
                ldsm4(r0, r1, r2, r3, bbase + (unsigned)((jp * 16 * AL + kk) * 2));
                bf[2 * jp][0] = r0; bf[2 * jp][1] = r1;
                bf[2 * jp + 1][0] = r2; bf[2 * jp + 1][1] = r3;
            }
            #pragma unroll
            for (int i = 0; i < 4; i++)
                #pragma unroll
                for (int j = 0; j < 8; j++)
                    mma_f16(acc[i][j], af[i], bf[j]);
        }
    };

    const int nk = K / BKH;
    #pragma unroll
    for (int s = 0; s < STAGES - 1; s++) {      // prefetch 2 tiles
        if (s < nk) issue(s, s * BKH);
        CP_COMMIT();
    }
    for (int kt = 0; kt < nk; kt++) {
        CP_WAIT1();                              // tile kt landed (kt+1 in flight)
        __syncthreads();
        compute(kt % STAGES);
        if (kt + STAGES - 1 < nk)
            issue((kt + STAGES - 1) % STAGES, (kt + STAGES - 1) * BKH);
        CP_COMMIT();
    }

    #pragma unroll
    for (int i = 0; i < 4; i++) {
        #pragma unroll
        for (int j = 0; j < 8; j++) {
            const long long row = bm + wm + i * 16 + g;
            const int       col = bn + wn + j * 8 + 2 * t;
            float2 v0 = make_float2(acc[i][j][0] * alpha, acc[i][j][1] * alpha);
            float2 v1 = make_float2(acc[i][j][2] * alpha, acc[i][j][3] * alpha);
            if (EPI == 2) {
                const float c = 0.70710678118654752f;
                v0.x = 0.5f * v0.x * erfcf(-v0.x * c);
                v0.y = 0.5f * v0.y * erfcf(-v0.y * c);
                v1.x = 0.5f * v1.x * erfcf(-v1.x * c);
                v1.y = 0.5f * v1.y * erfcf(-v1.y * c);
            }
            if (OUTHALF) {
                *(__half2*)&Ch[row * (long long)ldc + col]       = __floats2half2_rn(v0.x, v0.y);
                *(__half2*)&Ch[(row + 8) * (long long)ldc + col] = __floats2half2_rn(v1.x, v1.y);
            } else {
                *(float2*)&Cf[row * (long long)ldc + col]       = v0;
                *(float2*)&Cf[(row + 8) * (long long)ldc + col] = v1;
            }
        }
    }
}

// ---------------------------------------------------------------- flash v2: 2-pass, no P materialization
constexpr int FL_STRIDE = 136;                       // halves
constexpr int FL_TILE   = 128 * FL_STRIDE * 2;       // 34816 B
constexpr int FL_CS     = 8 * 128 * 4;               // 4096 B warp colsum buffer
constexpr int FL_SMEM   = 4 * FL_TILE + FL_CS;       // 143360 B

__global__ __launch_bounds__(256, 1) void flash2_k(
    const __half* __restrict__ qkv, float* __restrict__ part2,
    __half* __restrict__ y, float scale2)
{
    const int qb = blockIdx.x;
    const int bh = blockIdx.y;
    const int b  = bh >> 3;
    const int h  = bh & 7;
    const int D3 = 3 * Dd;

    const __half* Qp = qkv + ((long long)(b * Ss + qb * 128)) * D3 + h * HD;
    const __half* Kp = qkv + ((long long)b * Ss) * D3 + Dd + h * HD;
    const __half* Vp = qkv + ((long long)b * Ss) * D3 + 2 * Dd + h * HD;
    __half* yp = y + ((long long)(b * Ss + qb * 128)) * Dd + h * HD;
    float* p2p = part2 + ((size_t)bh * 8 + qb) * 1024;

    extern __shared__ __align__(16) char smemraw[];
    const unsigned sb = (unsigned)__cvta_generic_to_shared(smemraw);
    const unsigned kB0 = sb, kB1 = sb + FL_TILE;
    const unsigned vB0 = sb + 2 * FL_TILE, vB1 = sb + 3 * FL_TILE;
    float* sm_cs = (float*)(smemraw + 4 * FL_TILE);

    const int tid  = threadIdx.x;
    const int lane = tid & 31;
    const int warp = tid >> 5;
    const int wq   = warp * 16;
    const int g    = lane >> 2;
    const int t    = lane & 3;
    const int lp = lane >> 3, lr = lane & 7;
    const int aRowOff  = (lp & 1) * 8 + lr;
    const int aColOff  = (lp >> 1) * 8;
    const int bRowOff  = (lp >> 1) * 8 + lr;
    const int bColOff  = (lp & 1) * 8;
    const int ntRowOff = (lp & 1) * 8 + lr;
    const int ntColOff = (lp >> 1) * 8;

    auto loadTile = [&](unsigned dstB, const __half* src) {
        #pragma unroll
        for (int i2 = 0; i2 < 8; i2++) {
            int idx = i2 * 256 + tid;
            int r = idx >> 4, ch = idx & 15;
            cp_async16(dstB + (unsigned)((r * FL_STRIDE + ch * 8) * 2),
                       src + (long long)r * D3 + ch * 8);
        }
    };

    loadTile(vB0, Qp); CP_COMMIT();
    loadTile(kB0, Kp); CP_COMMIT();
    CP_WAIT1();
    __syncthreads();
    unsigned aQ[8][4];
    {
        const unsigned abase = vB0 + (unsigned)(((wq + aRowOff) * FL_STRIDE + aColOff) * 2);
        #pragma unroll
        for (int ks = 0; ks < 8; ks++)
            ldsm4(aQ[ks][0], aQ[ks][1], aQ[ks][2], aQ[ks][3],
                  abase + (unsigned)(ks * 32));
    }

    const int rloc0 = wq + g, rloc1 = rloc0 + 8;
    float m0 = -1e30f, m1 = -1e30f, l0 = 0.f, l1 = 0.f;

    auto computeS = [&](unsigned kbuf, float (*ct)[4], bool diag) {
        #pragma unroll
        for (int nt = 0; nt < 16; nt++) {
            ct[nt][0] = 0.f; ct[nt][1] = 0.f; ct[nt][2] = 0.f; ct[nt][3] = 0.f;
        }
        const unsigned bbase = kbuf + (unsigned)((bRowOff * FL_STRIDE + bColOff) * 2);
        #pragma unroll
        for (int ks = 0; ks < 8; ks++) {
            unsigned bf[16][2];
            #pragma unroll
            for (int jp = 0; jp < 8; jp++) {
                unsigned r0, r1, r2, r3;
                ldsm4(r0, r1, r2, r3,
                      bbase + (unsigned)((jp * 16 * FL_STRIDE + ks * 16) * 2));
                bf[2 * jp][0] = r0; bf[2 * jp][1] = r1;
                bf[2 * jp + 1][0] = r2; bf[2 * jp + 1][1] = r3;
            }
            #pragma unroll
            for (int nt = 0; nt < 16; nt++)
                mma_f16(ct[nt], aQ[ks], bf[nt]);
        }
        #pragma unroll
        for (int nt = 0; nt < 16; nt++) {
            #pragma unroll
            for (int e = 0; e < 2; e++) {
                float s0 = ct[nt][e]     * scale2;
                float s1 = ct[nt][2 + e] * scale2;
                if (diag) {
                    int col = nt * 8 + 2 * t + e;
                    if (col > rloc0) s0 = -1e30f;
                    if (col > rloc1) s1 = -1e30f;
                }
                ct[nt][e] = s0; ct[nt][2 + e] = s1;
            }
        }
    };

    // pass 1: softmax stats
    for (int kb = 0; kb <= qb; kb++) {
        const int cur = kb & 1;
        if (kb < qb) loadTile(cur ? kB0 : kB1, Kp + (long long)(kb + 1) * 128 * D3);
        CP_COMMIT();
        CP_WAIT1();
        __syncthreads();

        float ct[16][4];
        computeS(cur ? kB1 : kB0, ct, kb == qb);

        float mx0 = -1e30f, mx1 = -1e30f;
        #pragma unroll
        for (int nt = 0; nt < 16; nt++) {
            mx0 = fmaxf(mx0, fmaxf(ct[nt][0], ct[nt][1]));
            mx1 = fmaxf(mx1, fmaxf(ct[nt][2], ct[nt][3]));
        }
        mx0 = fmaxf(mx0, __shfl_xor_sync(0xffffffffu, mx0, 1));
        mx0 = fmaxf(mx0, __shfl_xor_sync(0xffffffffu, mx0, 2));
        mx1 = fmaxf(mx1, __shfl_xor_sync(0xffffffffu, mx1, 1));
        mx1 = fmaxf(mx1, __shfl_xor_sync(0xffffffffu, mx1, 2));
        const float m0n = fmaxf(m0, mx0), m1n = fmaxf(m1, mx1);
        const float f0 = exp2f(m0 - m0n), f1 = exp2f(m1 - m1n);
        float rs0 = 0.f, rs1 = 0.f;
        #pragma unroll
        for (int nt = 0; nt < 16; nt++) {
            rs0 += exp2f(ct[nt][0] - m0n) + exp2f(ct[nt][1] - m0n);
            rs1 += exp2f(ct[nt][2] - m1n) + exp2f(ct[nt][3] - m1n);
        }
        rs0 += __shfl_xor_sync(0xffffffffu, rs0, 1);
        rs0 += __shfl_xor_sync(0xffffffffu, rs0, 2);
        rs1 += __shfl_xor_sync(0xffffffffu, rs1, 1);
        rs1 += __shfl_xor_sync(0xffffffffu, rs1, 2);
        l0 = l0 * f0 + rs0;
        l1 = l1 * f1 + rs1;
        m0 = m0n; m1 = m1n;
        __syncthreads();
    }
    const float inv0 = 1.f / l0, inv1 = 1.f / l1;

    // pass 2: P, O, column sums
    float oc[16][4];
    #pragma unroll
    for (int nt = 0; nt < 16; nt++) {
        oc[nt][0] = 0.f; oc[nt][1] = 0.f; oc[nt][2] = 0.f; oc[nt][3] = 0.f;
    }
    loadTile(kB0, Kp); loadTile(vB0, Vp); CP_COMMIT();
    for (int kb = 0; kb <= qb; kb++) {
        const int cur = kb & 1;
        if (kb < qb) {
            loadTile(cur ? kB0 : kB1, Kp + (long long)(kb + 1) * 128 * D3);
            loadTile(cur ? vB0 : vB1, Vp + (long long)(kb + 1) * 128 * D3);
        }
        CP_COMMIT();
        CP_WAIT1();
        __syncthreads();

        float ct[16][4];
        computeS(cur ? kB1 : kB0, ct, kb == qb);
        #pragma unroll
        for (int nt = 0; nt < 16; nt++) {
            ct[nt][0] = exp2f(ct[nt][0] - m0) * inv0;
            ct[nt][1] = exp2f(ct[nt][1] - m0) * inv0;
            ct[nt][2] = exp2f(ct[nt][2] - m1) * inv1;
            ct[nt][3] = exp2f(ct[nt][3] - m1) * inv1;
        }

        #pragma unroll
        for (int nt = 0; nt < 16; nt++) {
            float c0 = ct[nt][0] + ct[nt][2];
            float c1 = ct[nt][1] + ct[nt][3];
            c0 += __shfl_xor_sync(0xffffffffu, c0, 4);
            c0 += __shfl_xor_sync(0xffffffffu, c0, 8);
            c0 += __shfl_xor_sync(0xffffffffu, c0, 16);
            c1 += __shfl_xor_sync(0xffffffffu, c1, 4);
            c1 += __shfl_xor_sync(0xffffffffu, c1, 8);
            c1 += __shfl_xor_sync(0xffffffffu, c1, 16);
            if (lane < 4) {
                sm_cs[warp * 128 + nt * 8 + 2 * t]     = c0;
                sm_cs[warp * 128 + nt * 8 + 2 * t + 1] = c1;
            }
        }

        {
            const unsigned vbase = (cur ? vB1 : vB0)
                                 + (unsigned)((ntRowOff * FL_STRIDE + ntColOff) * 2);
            #pragma unroll
            for (int ks = 0; ks < 8; ks++) {
                unsigned aP[4];
                aP[0] = h2u(ct[2 * ks][0],     ct[2 * ks][1]);
                aP[1] = h2u(ct[2 * ks][2],     ct[2 * ks][3]);
                aP[2] = h2u(ct[2 * ks + 1][0], ct[2 * ks + 1][1]);
                aP[3] = h2u(ct[2 * ks + 1][2], ct[2 * ks + 1][3]);
                unsigned bf[16][2];
                #pragma unroll
                for (int jp = 0; jp < 8; jp++) {
                    unsigned r0, r1, r2, r3;
                    ldsm4t(r0, r1, r2, r3,
                           vbase + (unsigned)((ks * 16 * FL_STRIDE + jp * 16) * 2));
                    bf[2 * jp][0] = r0; bf[2 * jp][1] = r1;
                    bf[2 * jp + 1][0] = r2; bf[2 * jp + 1][1] = r3;
                }
                #pragma unroll
                for (int nt = 0; nt < 16; nt++)
                    mma_f16(oc[nt], aP, bf[nt]);
            }
        }
        __syncthreads();
        if (tid < 128) {
            float s = 0.f;
            #pragma unroll
            for (int w = 0; w < 8; w++) s += sm_cs[w * 128 + tid];
            p2p[kb * 128 + tid] = s;
        }
        __syncthreads();
    }

    __half2* y0 = (__half2*)(yp + (long long)rloc0 * Dd + 2 * t);
    __half2* y1 = (__half2*)(yp + (long long)rloc1 * Dd + 2 * t);
    #pragma unroll
    for (int nt = 0; nt < 16; nt++) {
        y0[nt * 4] = __floats2half2_rn(oc[nt][0], oc[nt][1]);
        y1[nt * 4] = __floats2half2_rn(oc[nt][2], oc[nt][3]);
    }
}

// ---------------------------------------------------------------- amap accumulate (fixed order)
__global__ __launch_bounds__(256) void amap_k(
    const float* __restrict__ part2, float* __restrict__ amap)
{
    const int i = blockIdx.x * 256 + threadIdx.x;   // 0..2047
    const int b = i >> 10, k = i & 1023;
    const int qb0 = k >> 7;
    float s = 0.f;
    for (int h = 0; h < Hh; h++)
        for (int qb = qb0; qb < 8; qb++)
            s += part2[(((size_t)(b * Hh + h)) * 8 + qb) * 1024 + k];
    amap[i] += s;
}

// ---------------------------------------------------------------- fused split-K reduce (+bias)(+snapshot)(+LN -> half xn)
template<int P, bool BIAS, bool SNAP, bool OUTLN>
__global__ __launch_bounds__(256) void reduce_ln_k(
    const float4* __restrict__ part, float4* __restrict__ x,
    const float* __restrict__ bias, float4* __restrict__ st, int layer,
    const float* __restrict__ g, const float* __restrict__ b,
    __half* __restrict__ xn)
{
    __shared__ float sm0[8], sm1[8];
    const int row = blockIdx.x, tid = threadIdx.x;
    const int i = row * 256 + tid;
    constexpr int N4 = BS * Dd / 4;

    float4 s = part[i];
    #pragma unroll
    for (int p = 1; p < P; p++) {
        float4 v = part[(size_t)p * N4 + i];
        s.x += v.x; s.y += v.y; s.z += v.z; s.w += v.w;
    }
    if (BIAS) {
        float4 bb = ((const float4*)bias)[tid];
        s.x += bb.x; s.y += bb.y; s.z += bb.z; s.w += bb.w;
    }
    float4 v = x[i];
    v.x += s.x; v.y += s.y; v.z += s.z; v.w += s.w;
    x[i] = v;
    if (SNAP)
        st[((long long)row * DEPTH + layer) * 256 + tid] = v;

    if (OUTLN) {
        float su  = v.x + v.y + v.z + v.w;
        float su2 = v.x * v.x + v.y * v.y + v.z * v.z + v.w * v.w;
        #pragma unroll
        for (int o = 16; o > 0; o >>= 1) {
            su  += __shfl_xor_sync(0xffffffffu, su,  o);
            su2 += __shfl_xor_sync(0xffffffffu, su2, o);
        }
        if ((tid & 31) == 0) { sm0[tid >> 5] = su; sm1[tid >> 5] = su2; }
        __syncthreads();
        if (tid < 32) {
            su  = (tid < 8) ? sm0[tid] : 0.f;
            su2 = (tid < 8) ? sm1[tid] : 0.f;
            #pragma unroll
            for (int o = 4; o > 0; o >>= 1) {
                su  += __shfl_xor_sync(0xffffffffu, su,  o);
                su2 += __shfl_xor_sync(0xffffffffu, su2, o);
            }
            if (tid == 0) { sm0[0] = su; sm1[0] = su2; }
        }
        __syncthreads();
        const float mean = sm0[0] * (1.f / Dd);
        const float var  = sm1[0] * (1.f / Dd) - mean * mean;
        const float rstd = rsqrtf(var + 1e-5f);
        float4 gg = ((const float4*)g)[tid];
        float4 bb = ((const float4*)b)[tid];
        float4 o;
        o.x = (v.x - mean) * rstd * gg.x + bb.x;
        o.y = (v.y - mean) * rstd * gg.y + bb.y;
        o.z = (v.z - mean) * rstd * gg.z + bb.z;
        o.w = (v.w - mean) * rstd * gg.w + bb.w;
        __half2* oh = (__half2*)(xn + (long long)row * Dd);
        oh[2 * tid]     = __floats2half2_rn(o.x, o.y);
        oh[2 * tid + 1] = __floats2half2_rn(o.z, o.w);
    }
}

// ---------------------------------------------------------------- transpose + cvt to half (half2-packed writes)
__global__ __launch_bounds__(256) void transpose_cvt_k(
    const float* __restrict__ src, __half* __restrict__ dst,
    int R, int C, long long sSrc, long long sDst)
{
    __shared__ float tile[64][33];
    src += blockIdx.z * sSrc;
    dst += blockIdx.z * sDst;
    const int c0 = blockIdx.x * 32, r0 = blockIdx.y * 64;
    const int tid = threadIdx.x;
    #pragma unroll
    for (int it = 0; it < 8; it++) {
        int idx = it * 256 + tid;
        int r = idx >> 5, c = idx & 31;
        tile[r][c] = src[(long long)(r0 + r) * C + c0 + c];
    }
    __syncthreads();
    #pragma unroll
    for (int it = 0; it < 4; it++) {
        int idx = it * 256 + tid;
        int c = idx >> 5, j = idx & 31;
        __half2 h = __floats2half2_rn(tile[2 * j][c], tile[2 * j + 1][c]);
        *((__half2*)(dst + (long long)(c0 + c) * R + r0) + j) = h;
    }
}

// ---------------------------------------------------------------- LayerNorm (standalone)
template<bool OUTH>
__global__ __launch_bounds__(256) void ln_k(
    const float* __restrict__ x, const float* __restrict__ g,
    const float* __restrict__ b, void* __restrict__ outv)
{
    __shared__ float sm0[8], sm1[8];
    const int row = blockIdx.x, tid = threadIdx.x;
    float4 v = ((const float4*)(x + (long long)row * Dd))[tid];
    float s  = v.x + v.y + v.z + v.w;
    float s2 = v.x * v.x + v.y * v.y + v.z * v.z + v.w * v.w;
    #pragma unroll
    for (int o = 16; o > 0; o >>= 1) {
        s  += __shfl_xor_sync(0xffffffffu, s,  o);
        s2 += __shfl_xor_sync(0xffffffffu, s2, o);
    }
    if ((tid & 31) == 0) { sm0[tid >> 5] = s; sm1[tid >> 5] = s2; }
    __syncthreads();
    if (tid < 32) {
        s  = (tid < 8) ? sm0[tid] : 0.f;
        s2 = (tid < 8) ? sm1[tid] : 0.f;
        #pragma unroll
        for (int o = 4; o > 0; o >>= 1) {
            s  += __shfl_xor_sync(0xffffffffu, s,  o);
            s2 += __shfl_xor_sync(0xffffffffu, s2, o);
        }
        if (tid == 0) { sm0[0] = s; sm1[0] = s2; }
    }
    __syncthreads();
    const float mean = sm0[0] * (1.f / Dd);
    const float var  = sm1[0] * (1.f / Dd) - mean * mean;
    const float rstd = rsqrtf(var + 1e-5f);
    float4 gg = ((const float4*)g)[tid];
    float4 bb = ((const float4*)b)[tid];
    float4 o;
    o.x = (v.x - mean) * rstd * gg.x + bb.x;
    o.y = (v.y - mean) * rstd * gg.y + bb.y;
    o.z = (v.z - mean) * rstd * gg.z + bb.z;
    o.w = (v.w - mean) * rstd * gg.w + bb.w;
    if (OUTH) {
        __half2* oh = (__half2*)((__half*)outv + (long long)row * Dd);
        oh[2 * tid]     = __floats2half2_rn(o.x, o.y);
        oh[2 * tid + 1] = __floats2half2_rn(o.z, o.w);
    } else {
        ((float4*)((float*)outv + (long long)row * Dd))[tid] = o;
    }
}

// ---------------------------------------------------------------- misc
__global__ __launch_bounds__(256) void init_x_snap_k(
    const float4* __restrict__ token, float4* __restrict__ x,
    float4* __restrict__ st)
{
    const int i = blockIdx.x * 256 + threadIdx.x;
    float4 v = token[i];
    x[i] = v;
    st[((long long)(i >> 8) * DEPTH + 0) * 256 + (i & 255)] = v;
}

__global__ void zero_k(float* p, int n)
{
    int i = blockIdx.x * 256 + threadIdx.x;
    if (i < n) p[i] = 0.f;
}

// ---------------------------------------------------------------- launcher
extern "C" void kernel_launch(void* const* d_in, const int* in_sizes, int n_in,
                              void* d_out, int out_size)
{
    const float* token = (const float*)d_in[0];
    const float* Wq    = (const float*)d_in[1];
    const float* Wkv   = (const float*)d_in[2];
    const float* Wo    = (const float*)d_in[3];
    const float* b_o   = (const float*)d_in[4];
    const float* g1    = (const float*)d_in[5];
    const float* b1    = (const float*)d_in[6];
    const float* g3    = (const float*)d_in[7];
    const float* b3    = (const float*)d_in[8];
    const float* W1    = (const float*)d_in[9];
    const float* W2    = (const float*)d_in[10];
    const float* gout  = (const float*)d_in[11];
    const float* bout  = (const float*)d_in[12];
    float* out = (float*)d_out;

    float *x, *red, *part2;
    __half *xn, *qkv, *wqkvT, *woT, *w1T, *w2T, *y, *ff;
    cudaGetSymbolAddress((void**)&x,     g_x);
    cudaGetSymbolAddress((void**)&xn,    g_xn);
    cudaGetSymbolAddress((void**)&qkv,   g_qkv);
    cudaGetSymbolAddress((void**)&wqkvT, g_wqkvT);
    cudaGetSymbolAddress((void**)&woT,   g_woT);
    cudaGetSymbolAddress((void**)&w1T,   g_w1T);
    cudaGetSymbolAddress((void**)&w2T,   g_w2T);
    cudaGetSymbolAddress((void**)&part2, g_part2);
    cudaGetSymbolAddress((void**)&y,     g_y);
    cudaGetSymbolAddress((void**)&ff,    g_ff);
    cudaGetSymbolAddress((void**)&red,   g_red);

    cudaFuncSetAttribute(gemm_h<0, true >, cudaFuncAttributeMaxDynamicSharedMemorySize, GEMM_SMEM);
    cudaFuncSetAttribute(gemm_h<0, false>, cudaFuncAttributeMaxDynamicSharedMemorySize, GEMM_SMEM);
    cudaFuncSetAttribute(gemm_h<2, true >, cudaFuncAttributeMaxDynamicSharedMemorySize, GEMM_SMEM);
    cudaFuncSetAttribute(flash2_k, cudaFuncAttributeMaxDynamicSharedMemorySize, FL_SMEM);

    float* out_state = out + (size_t)BS * Dd;
    float* amap      = out_state + (size_t)BS * DEPTH * Dd;

    init_x_snap_k<<<BS * Dd / 4 / 256, 256>>>((const float4*)token, (float4*)x,
                                              (float4*)out_state);
    zero_k<<<(BS + 255) / 256, 256>>>(amap, BS);

    const int D3 = 3 * Dd;
    transpose_cvt_k<<<dim3(Dd / 32, Dd / 64, DEPTH), 256>>>(
        Wq, wqkvT, Dd, Dd, (long long)Dd * Dd, (long long)D3 * Dd);
    transpose_cvt_k<<<dim3(2 * Dd / 32, Dd / 64, DEPTH), 256>>>(
        Wkv, wqkvT + (size_t)Dd * Dd, Dd, 2 * Dd,
        (long long)Dd * 2 * Dd, (long long)D3 * Dd);
    transpose_cvt_k<<<dim3(Dd / 32, Dd / 64, DEPTH), 256>>>(
        Wo, woT, Dd, Dd, (long long)Dd * Dd, (long long)Dd * Dd);
    transpose_cvt_k<<<dim3(FF / 32, Dd / 64, DEPTH), 256>>>(
        W1, w1T, Dd, FF, (long long)Dd * FF, (long long)Dd * FF);
    transpose_cvt_k<<<dim3(Dd / 32, FF / 64, DEPTH), 256>>>(
        W2, w2T, FF, Dd, (long long)FF * Dd, (long long)FF * Dd);

    const float scale2 = rsqrtf((float)HD) * 1.4426950408889634f;   // scale * log2(e)

    // layer-0 LN1
    ln_k<true><<<BS, 256>>>(x, g1, b1, xn);

    for (int l = 0; l < DEPTH; l++) {
        // QKV = xn @ [Wq|Wkv]^T
        gemm_h<0, true><<<dim3(D3 / BN, BS / BM, 1), 128, GEMM_SMEM>>>(
            xn, wqkvT + (size_t)l * D3 * Dd, qkv,
            Dd, Dd, Dd, D3, 0, 0, 0, 1.f);
        // fused attention: scores + softmax + colsum + A@V
        flash2_k<<<dim3(8, Bb * Hh), 256, FL_SMEM>>>(qkv, part2, y, scale2);
        // amap += column sums
        amap_k<<<Bb * Ss / 256, 256>>>(part2, amap);
        // Wo GEMM (split-K=2, fp32 partials)
        gemm_h<0, false><<<dim3(Dd / BN, BS / BM, 2), 128, GEMM_SMEM>>>(
            y, woT + (size_t)l * Dd * Dd, red,
            Dd / 2, Dd, Dd, Dd,
            Dd / 2, Dd / 2, (long long)BS * Dd, 1.f);
        reduce_ln_k<2, true, false, true><<<BS, 256>>>(
            (const float4*)red, (float4*)x, b_o + l * Dd, nullptr, 0,
            g3 + l * Dd, b3 + l * Dd, xn);
        // ff = gelu(xn @ W1^T)
        gemm_h<2, true><<<dim3(FF / BN, BS / BM, 1), 128, GEMM_SMEM>>>(
            xn, w1T + (size_t)l * FF * Dd, ff,
            Dd, Dd, Dd, FF, 0, 0, 0, 1.f);
        // FF2 GEMM (split-K=4)
        gemm_h<0, false><<<dim3(Dd / BN, BS / BM, 4), 128, GEMM_SMEM>>>(
            ff, w2T + (size_t)l * Dd * FF, red,
            FF / 4, FF, FF, Dd,
            FF / 4, FF / 4, (long long)BS * Dd, 1.f);
        if (l < DEPTH - 1)
            reduce_ln_k<4, false, true, true><<<BS, 256>>>(
                (const float4*)red, (float4*)x, nullptr, (float4*)out_state, l + 1,
                g1 + (l + 1) * Dd, b1 + (l + 1) * Dd, xn);
        else
            reduce_ln_k<4, false, false, false><<<BS, 256>>>(
                (const float4*)red, (float4*)x, nullptr, nullptr, 0,
                nullptr, nullptr, nullptr);
    }
    // final LN -> x_out (fp32)
    ln_k<false><<<BS, 256>>>(x, gout, bout, out);
}